// round 10
// baseline (speedup 1.0000x reference)
#include <cuda_runtime.h>
#include <cuda_fp16.h>
#include <cstdint>
#include <math.h>

#define Bb 8
#define Ss 2048
#define Ee 2048
#define Hh 16
#define Dd 128
#define PADTOK 50257

// ---------------- scratch (device globals: allocation-free) ----------------
__device__ __half g_hsH[(size_t)Bb * Ss * Ee];      // hi fp16 split of LN output
__device__ __half g_hsL[(size_t)Bb * Ss * Ee];      // lo fp16 split
__device__ __half g_pH[(size_t)Bb * Hh * 64 * Ee];  // projected weights hi (cos/sin coeffs)
__device__ __half g_pL[(size_t)Bb * Hh * 64 * Ee];  // projected weights lo
__device__ float g_Cv[(size_t)Bb * Hh * Ee];        // C vector per (b,h), fp32
__device__ float g_q[Bb * Ee];
__device__ float g_sc[Bb * Hh * Ss];
__device__ float g_c[Bb * Hh * Ee];
__device__ float g_oattn[Bb * Ee];
__device__ int   g_ix[Bb];

// ---------------- helpers ----------------
__device__ __forceinline__ void splitp_h(float f0, float f1, uint32_t& hi, uint32_t& lo) {
    __half2 Hv = __floats2half2_rn(f0, f1);
    float r0 = f0 - __low2float(Hv);
    float r1 = f1 - __high2float(Hv);
    __half2 Lv = __floats2half2_rn(r0, r1);
    hi = *reinterpret_cast<uint32_t*>(&Hv);
    lo = *reinterpret_cast<uint32_t*>(&Lv);
}

__device__ __forceinline__ float h2sum(uint32_t h, uint32_t l, int sel) {
    __half2 hv = *reinterpret_cast<__half2*>(&h);
    __half2 lv = *reinterpret_cast<__half2*>(&l);
    return sel ? (__high2float(hv) + __high2float(lv))
               : (__low2float(hv) + __low2float(lv));
}

// ---------------- LayerNorm + fp16 hi/lo split ----------------
__global__ __launch_bounds__(256) void ln_kernel(const float* __restrict__ x,
                                                 const float* __restrict__ w,
                                                 const float* __restrict__ bias) {
    int row = blockIdx.x;
    const float4* xin = reinterpret_cast<const float4*>(x + (size_t)row * Ee);
    int tid = threadIdx.x;
    float4 v0 = xin[tid];
    float4 v1 = xin[tid + 256];
    float s  = v0.x + v0.y + v0.z + v0.w + v1.x + v1.y + v1.z + v1.w;
    float s2 = v0.x*v0.x + v0.y*v0.y + v0.z*v0.z + v0.w*v0.w
             + v1.x*v1.x + v1.y*v1.y + v1.z*v1.z + v1.w*v1.w;
    #pragma unroll
    for (int o = 16; o; o >>= 1) {
        s  += __shfl_xor_sync(0xffffffffu, s, o);
        s2 += __shfl_xor_sync(0xffffffffu, s2, o);
    }
    __shared__ float red[16];
    __shared__ float mv[2];
    int warp = tid >> 5, lane = tid & 31;
    if (lane == 0) { red[warp] = s; red[warp + 8] = s2; }
    __syncthreads();
    if (tid == 0) {
        float a = 0.f, b2 = 0.f;
        #pragma unroll
        for (int i = 0; i < 8; i++) { a += red[i]; b2 += red[i + 8]; }
        float mu  = a / (float)Ee;
        float var = b2 / (float)Ee - mu * mu;
        mv[0] = mu; mv[1] = rsqrtf(var + 1e-5f);
    }
    __syncthreads();
    float mu = mv[0], rs = mv[1];
    const float4* wv4 = reinterpret_cast<const float4*>(w);
    const float4* bv4 = reinterpret_cast<const float4*>(bias);
    uint2* outH = reinterpret_cast<uint2*>(g_hsH + (size_t)row * Ee);
    uint2* outL = reinterpret_cast<uint2*>(g_hsL + (size_t)row * Ee);
    {
        float4 wv = wv4[tid], bv = bv4[tid], o;
        o.x = (v0.x - mu) * rs * wv.x + bv.x;
        o.y = (v0.y - mu) * rs * wv.y + bv.y;
        o.z = (v0.z - mu) * rs * wv.z + bv.z;
        o.w = (v0.w - mu) * rs * wv.w + bv.w;
        uint32_t h0, l0, h1, l1;
        splitp_h(o.x, o.y, h0, l0); splitp_h(o.z, o.w, h1, l1);
        outH[tid] = make_uint2(h0, h1);
        outL[tid] = make_uint2(l0, l1);
    }
    {
        float4 wv = wv4[tid + 256], bv = bv4[tid + 256], o;
        o.x = (v1.x - mu) * rs * wv.x + bv.x;
        o.y = (v1.y - mu) * rs * wv.y + bv.y;
        o.z = (v1.z - mu) * rs * wv.z + bv.z;
        o.w = (v1.w - mu) * rs * wv.w + bv.w;
        uint32_t h0, l0, h1, l1;
        splitp_h(o.x, o.y, h0, l0); splitp_h(o.z, o.w, h1, l1);
        outH[tid + 256] = make_uint2(h0, h1);
        outL[tid + 256] = make_uint2(l0, l1);
    }
}

// ---------------- last non-pad index ----------------
__global__ __launch_bounds__(256) void ix_kernel(const int* __restrict__ ids) {
    int b = blockIdx.x;
    int m = -1;
    for (int s = threadIdx.x; s < Ss; s += 256)
        if (ids[b * Ss + s] != PADTOK) m = s;
    #pragma unroll
    for (int o = 16; o; o >>= 1) m = max(m, __shfl_xor_sync(0xffffffffu, m, o));
    __shared__ int rm[8];
    int warp = threadIdx.x >> 5, lane = threadIdx.x & 31;
    if (lane == 0) rm[warp] = m;
    __syncthreads();
    if (threadIdx.x == 0) {
        int mm = -1;
        #pragma unroll
        for (int i = 0; i < 8; i++) mm = max(mm, rm[i]);
        g_ix[b] = (mm < 0) ? 0 : mm;
    }
}

// ---------------- fused q + P-matrix kernel (per (h, b) block) ----------------
__global__ __launch_bounds__(256) void qpmat_kernel(const float* __restrict__ qw,
                                                    const float* __restrict__ qb,
                                                    const float* __restrict__ kw) {
    __shared__ float qs[128];
    const int tid = threadIdx.x, warp = tid >> 5, lane = tid & 31;
    const int h = blockIdx.x, b = blockIdx.y;

    size_t hb = ((size_t)(b * Ss) + g_ix[b]) * Ee;
    const uint2* hH = reinterpret_cast<const uint2*>(g_hsH + hb);
    const uint2* hL = reinterpret_cast<const uint2*>(g_hsL + hb);

    for (int rr = 0; rr < 16; rr++) {
        int d = warp * 16 + rr;
        int j = h * 128 + d;
        const float4* wrow = reinterpret_cast<const float4*>(qw + (size_t)j * Ee);
        float acc = 0.f;
        #pragma unroll
        for (int it = 0; it < 16; it++) {
            int i4 = it * 32 + lane;
            uint2 hv = hH[i4], lv = hL[i4];
            float4 w = wrow[i4];
            acc += h2sum(hv.x, lv.x, 0) * w.x;
            acc += h2sum(hv.x, lv.x, 1) * w.y;
            acc += h2sum(hv.y, lv.y, 0) * w.z;
            acc += h2sum(hv.y, lv.y, 1) * w.w;
        }
        #pragma unroll
        for (int o = 16; o; o >>= 1) acc += __shfl_xor_sync(0xffffffffu, acc, o);
        if (lane == 0) {
            float v = acc + qb[j];
            qs[d] = v;
            g_q[b * Ee + j] = v;
        }
    }
    __syncthreads();

    #pragma unroll
    for (int i = 0; i < 8; i++) {
        int e = tid + 256 * i;
        size_t pbase = ((size_t)(b * Hh + h)) * 64 * Ee + e;
        const float* kwb = kw + (size_t)h * Dd * Ee + e;
        #pragma unroll 4
        for (int j = 0; j < 32; j++) {
            float k0 = kwb[(size_t)(2 * j) * Ee];
            float k1 = kwb[(size_t)(2 * j + 1) * Ee];
            float A  = k0 * qs[2 * j]     + k1 * qs[2 * j + 1];
            float Bv = k0 * qs[2 * j + 1] - k1 * qs[2 * j];
            __half ah = __float2half_rn(A);
            __half al = __float2half_rn(A - __half2float(ah));
            __half bh = __float2half_rn(Bv);
            __half bl = __float2half_rn(Bv - __half2float(bh));
            g_pH[pbase + (size_t)j * Ee] = ah;
            g_pL[pbase + (size_t)j * Ee] = al;
            g_pH[pbase + (size_t)(32 + j) * Ee] = bh;
            g_pL[pbase + (size_t)(32 + j) * Ee] = bl;
        }
        float C = 0.f;
        #pragma unroll 8
        for (int d = 64; d < 128; d++) C += kwb[(size_t)d * Ee] * qs[d];
        g_Cv[(size_t)(b * Hh + h) * Ee + e] = C;
    }
}

// ---------------- GEMM G = hs @ P^T : M64 x N64 (1 head) per CTA, 3 CTAs/SM ----
__device__ __forceinline__ void mma_f16(float c[4], uint32_t a0, uint32_t a1, uint32_t a2,
                                        uint32_t a3, uint32_t b0, uint32_t b1) {
    asm volatile(
        "mma.sync.aligned.m16n8k16.row.col.f32.f16.f16.f32 "
        "{%0,%1,%2,%3}, {%4,%5,%6,%7}, {%8,%9}, {%0,%1,%2,%3};"
        : "+f"(c[0]), "+f"(c[1]), "+f"(c[2]), "+f"(c[3])
        : "r"(a0), "r"(a1), "r"(a2), "r"(a3), "r"(b0), "r"(b1));
}

__device__ __forceinline__ void ldsm4(uint32_t r[4], uint32_t a) {
    asm volatile("ldmatrix.sync.aligned.m8n8.x4.shared.b16 {%0,%1,%2,%3}, [%4];"
                 : "=r"(r[0]), "=r"(r[1]), "=r"(r[2]), "=r"(r[3]) : "r"(a));
}

__device__ __forceinline__ void cp16(uint32_t dst, const void* src) {
    asm volatile("cp.async.cg.shared.global [%0], [%1], 16;" :: "r"(dst), "l"(src) : "memory");
}
#define CP_COMMIT() asm volatile("cp.async.commit_group;" ::: "memory")
#define CP_WAIT1()  asm volatile("cp.async.wait_group 1;" ::: "memory")
#define CP_WAIT0()  asm volatile("cp.async.wait_group 0;" ::: "memory")

// stage layout (byte offsets), K64 chunk: A 64x128B per limb, B 64x128B per limb
#define GA_H 0
#define GA_L 8192
#define GB_H 16384
#define GB_L 24576
#define GM_STAGE 32768
#define GEMM_SMEM (2 * GM_STAGE)      // 64 KB dynamic

__global__ void __launch_bounds__(256, 3) gemm_scores(const float* __restrict__ kb) {
    extern __shared__ char dsm[];
    __shared__ __align__(16) float pbA[32], pbB[32], pbC[4];
    __shared__ __align__(16) double finv[32];
    __shared__ __align__(16) float Cs[2048];
    __shared__ __align__(16) float cred[64][4];
    __shared__ __align__(16) float part[64][4];

    const int tid = threadIdx.x, warp = tid >> 5, lane = tid & 31;
    const int bh = blockIdx.x, b = bh >> 4, h = bh & 15;   // bh fast: L2 A-sharing
    const int s0 = blockIdx.y * 64;

    if (tid < 32) {
        finv[tid] = exp(-((double)(2 * tid) / 64.0) * 9.210340371976184);
        float q0 = g_q[b * Ee + h * Dd + 2 * tid];
        float q1 = g_q[b * Ee + h * Dd + 2 * tid + 1];
        float k0 = kb[h * Dd + 2 * tid];
        float k1 = kb[h * Dd + 2 * tid + 1];
        pbA[tid] = q0 * k0 + q1 * k1;
        pbB[tid] = q1 * k0 - q0 * k1;
    } else if (tid == 32) {
        float a = 0.f;
        for (int d = 64; d < 128; d++) a += kb[h * Dd + d] * g_q[b * Ee + h * Dd + d];
        pbC[0] = a;
    }
    // C vector -> smem (fp32, 8KB)
    {
        const float4* cv = reinterpret_cast<const float4*>(g_Cv + (size_t)bh * Ee);
        #pragma unroll
        for (int i = 0; i < 2; i++) {
            float4 v = cv[tid + i * 256];
            *reinterpret_cast<float4*>(&Cs[(tid + i * 256) * 4]) = v;
        }
    }

    uint32_t sb;
    asm("{ .reg .u64 t; cvta.to.shared.u64 t, %1; cvt.u32.u64 %0, t; }" : "=r"(sb) : "l"(dsm));

    const char* aHb = (const char*)(g_hsH + (size_t)(b * Ss + s0) * Ee);
    const char* aLb = (const char*)(g_hsL + (size_t)(b * Ss + s0) * Ee);
    const char* pHb = (const char*)(g_pH + (size_t)bh * 64 * Ee);
    const char* pLb = (const char*)(g_pL + (size_t)bh * 64 * Ee);

// 2048 cp16 per stage (8 per thread): each array 64 rows x 8 x 16B
#define G_LOAD_STAGE(st, k0w)                                                     \
    {                                                                             \
        uint32_t sbase = sb + (st) * GM_STAGE;                                    \
        _Pragma("unroll")                                                         \
        for (int i = 0; i < 8; i++) {                                             \
            int id = tid + 256 * i;                                               \
            int arr = id >> 9;                                                    \
            int rid = id & 511;                                                   \
            int row = rid >> 3, c = rid & 7;                                      \
            uint32_t aoff = (arr == 0) ? GA_H : (arr == 1) ? GA_L                 \
                            : (arr == 2) ? GB_H : GB_L;                           \
            const char* src = (arr == 0) ? aHb : (arr == 1) ? aLb                 \
                             : (arr == 2) ? pHb : pLb;                            \
            uint32_t dst = sbase + aoff +                                         \
                (uint32_t)(row * 128 + ((c ^ (row & 7)) << 4));                   \
            cp16(dst, src + (size_t)row * 4096 + (size_t)(k0w) * 2 + c * 16);     \
        }                                                                         \
        CP_COMMIT();                                                              \
    }

    float acc[2][2][4];
    #pragma unroll
    for (int i = 0; i < 2; i++)
        #pragma unroll
        for (int j = 0; j < 2; j++)
            #pragma unroll
            for (int k = 0; k < 4; k++) acc[i][j][k] = 0.f;
    float cacc[2][2] = {{0.f, 0.f}, {0.f, 0.f}};

    const int wM = warp >> 2, wN = warp & 3;   // 2 x 4 warps
    const int rA = wM * 32, nb = wN * 16;
    const int g = lane >> 2, tq = lane & 3;

    G_LOAD_STAGE(0, 0);

    for (int k = 0; k < 32; k++) {
        const int s = k & 1;
        const int k0w = k * 64;
        if (k + 1 < 32) { G_LOAD_STAGE(s ^ 1, (k + 1) * 64); CP_WAIT1(); }
        else            { CP_WAIT0(); }
        __syncthreads();
        uint32_t base = sb + s * GM_STAGE;

        #pragma unroll
        for (int kk = 0; kk < 4; kk++) {
            const int kkc = kk * 2;
            uint32_t aH[2][4], aL[2][4];
            #pragma unroll
            for (int mt = 0; mt < 2; mt++) {
                int row = rA + mt * 16 + (lane & 15);
                int c16 = kkc + (lane >> 4);
                uint32_t off = (uint32_t)(row * 128 + ((c16 ^ (row & 7)) << 4));
                ldsm4(aH[mt], base + GA_H + off);
                ldsm4(aL[mt], base + GA_L + off);
            }
            uint32_t bH[4], bL[4];
            {
                int row = nb + ((lane >> 4) << 3) + (lane & 7);
                int c16 = kkc + ((lane >> 3) & 1);
                uint32_t off = (uint32_t)(row * 128 + ((c16 ^ (row & 7)) << 4));
                ldsm4(bH, base + GB_H + off);
                ldsm4(bL, base + GB_L + off);
            }
            // in-register C-dot on the fma pipe: warp wN handles kk == wN
            if (kk == wN) {
                #pragma unroll
                for (int mt = 0; mt < 2; mt++) {
                    #pragma unroll
                    for (int r = 0; r < 4; r++) {
                        float2 fh = __half22float2(*reinterpret_cast<__half2*>(&aH[mt][r]));
                        float2 fl = __half22float2(*reinterpret_cast<__half2*>(&aL[mt][r]));
                        int ki = k0w + kk * 16 + tq * 2 + ((r & 2) ? 8 : 0);
                        cacc[mt][r & 1] += (fh.x + fl.x) * Cs[ki] + (fh.y + fl.y) * Cs[ki + 1];
                    }
                }
            }
            #pragma unroll
            for (int nt = 0; nt < 2; nt++) {
                #pragma unroll
                for (int mt = 0; mt < 2; mt++) {
                    mma_f16(acc[mt][nt], aH[mt][0], aH[mt][1], aH[mt][2], aH[mt][3],
                            bH[nt * 2], bH[nt * 2 + 1]);
                    mma_f16(acc[mt][nt], aL[mt][0], aL[mt][1], aL[mt][2], aL[mt][3],
                            bH[nt * 2], bH[nt * 2 + 1]);
                    mma_f16(acc[mt][nt], aH[mt][0], aH[mt][1], aH[mt][2], aH[mt][3],
                            bL[nt * 2], bL[nt * 2 + 1]);
                }
            }
        }
        __syncthreads();
    }

    // reduce C-dot partials over the 4 tq lanes
    #pragma unroll
    for (int mt = 0; mt < 2; mt++) {
        #pragma unroll
        for (int rr = 0; rr < 2; rr++) {
            float p = cacc[mt][rr];
            p += __shfl_xor_sync(0xffffffffu, p, 1);
            p += __shfl_xor_sync(0xffffffffu, p, 2);
            if (tq == 0) cred[rA + mt * 16 + rr * 8 + g][wN] = p;
        }
    }

    // acc -> smem G tile [64][65] (reuses stage-0 bytes; all MMAs done)
    float* Gs = reinterpret_cast<float*>(dsm);
    #pragma unroll
    for (int nt = 0; nt < 2; nt++) {
        #pragma unroll
        for (int mt = 0; mt < 2; mt++) {
            int r = rA + mt * 16 + (lane >> 2);
            int n = nb + nt * 8 + 2 * (lane & 3);
            float* g0 = Gs + r * 65 + n;
            g0[0] = acc[mt][nt][0];
            g0[1] = acc[mt][nt][1];
            g0[65 * 8] = acc[mt][nt][2];
            g0[65 * 8 + 1] = acc[mt][nt][3];
        }
    }
    __syncthreads();

    // combine: 256 threads, 4 per row (8 j's each), then reduce
    {
        const double INV2PI = 0.15915494309189535;
        const double TWOPI  = 6.283185307179586;
        int row = tid & 63, qq = tid >> 6;
        int s = s0 + row;
        const float* rp = Gs + row * 65;
        float p = 0.f;
        #pragma unroll
        for (int jj = 0; jj < 8; jj++) {
            int j = qq * 8 + jj;
            double ang = (double)s * finv[j];
            double kq = rint(ang * INV2PI);
            float r = (float)(ang - kq * TWOPI);
            float sn, cs;
            __sincosf(r, &sn, &cs);
            p += cs * (rp[j] + pbA[j]) + sn * (rp[32 + j] + pbB[j]);
        }
        part[row][qq] = p;
    }
    __syncthreads();
    if (tid < 64) {
        float accS = pbC[0] + cred[tid][0] + cred[tid][1] + cred[tid][2] + cred[tid][3]
                   + part[tid][0] + part[tid][1] + part[tid][2] + part[tid][3];
        g_sc[(size_t)bh * Ss + s0 + tid] = accS;
    }
}

// ---------------- softmax over s (per b,h) ----------------
__global__ __launch_bounds__(256) void softmax_kernel() {
    int row = blockIdx.x;
    float* pp = g_sc + (size_t)row * Ss;
    int tid = threadIdx.x;
    float v[8];
    float m = -1e30f;
    #pragma unroll
    for (int i = 0; i < 8; i++) { v[i] = pp[tid + i * 256]; m = fmaxf(m, v[i]); }
    #pragma unroll
    for (int o = 16; o; o >>= 1) m = fmaxf(m, __shfl_xor_sync(0xffffffffu, m, o));
    __shared__ float rs[8];
    int warp = tid >> 5, lane = tid & 31;
    if (lane == 0) rs[warp] = m;
    __syncthreads();
    float mm = rs[0];
    #pragma unroll
    for (int i = 1; i < 8; i++) mm = fmaxf(mm, rs[i]);
    float ssum = 0.f;
    #pragma unroll
    for (int i = 0; i < 8; i++) { v[i] = expf(v[i] - mm); ssum += v[i]; }
    #pragma unroll
    for (int o = 16; o; o >>= 1) ssum += __shfl_xor_sync(0xffffffffu, ssum, o);
    __syncthreads();
    if (lane == 0) rs[warp] = ssum;
    __syncthreads();
    float tot = 0.f;
    #pragma unroll
    for (int i = 0; i < 8; i++) tot += rs[i];
    float inv = 1.f / tot;
    #pragma unroll
    for (int i = 0; i < 8; i++) pp[tid + i * 256] = v[i] * inv;
}

// ---------------- c[b,h,e] = sum_s attn * hs ----------------
__global__ void zero_c_kernel() {
    int i = blockIdx.x * blockDim.x + threadIdx.x;
    if (i < Bb * Hh * Ee) g_c[i] = 0.f;
}

__global__ __launch_bounds__(128) void cvec_kernel() {
    __shared__ float at[16][128];
    int tid = threadIdx.x;
    int b = blockIdx.y;
    int e = blockIdx.x * 128 + tid;
    int sbase = blockIdx.z * 256;
    float acc[16];
    #pragma unroll
    for (int i = 0; i < 16; i++) acc[i] = 0.f;
    for (int sc = 0; sc < 256; sc += 128) {
        #pragma unroll
        for (int i = 0; i < 16; i++) {
            int idx = tid + i * 128;
            int hh = idx >> 7, si = idx & 127;
            at[hh][si] = g_sc[(size_t)(b * Hh + hh) * Ss + sbase + sc + si];
        }
        __syncthreads();
        size_t base = (size_t)(b * Ss + sbase + sc) * Ee + e;
        #pragma unroll 4
        for (int si = 0; si < 128; si++) {
            float x = __half2float(g_hsH[base + (size_t)si * Ee])
                    + __half2float(g_hsL[base + (size_t)si * Ee]);
            #pragma unroll
            for (int hh = 0; hh < 16; hh++) acc[hh] += at[hh][si] * x;
        }
        __syncthreads();
    }
    #pragma unroll
    for (int hh = 0; hh < 16; hh++)
        atomicAdd(&g_c[(size_t)(b * Hh + hh) * Ee + e], acc[hh]);
}

// ---------------- out_attn = c @ v_w.T (per head) + v_b ----------------
__global__ __launch_bounds__(256) void vproj_kernel(const float* __restrict__ vw,
                                                    const float* __restrict__ vb) {
    int b = blockIdx.y;
    int warp = threadIdx.x >> 5, lane = threadIdx.x & 31;
    int j = blockIdx.x * 8 + warp;
    int hh = j >> 7;
    const float4* crow = reinterpret_cast<const float4*>(g_c + (size_t)(b * Hh + hh) * Ee);
    const float4* wrow = reinterpret_cast<const float4*>(vw + (size_t)j * Ee);
    float acc = 0.f;
    #pragma unroll
    for (int it = 0; it < 16; it++) {
        int i4 = it * 32 + lane;
        float4 a = crow[i4], w = wrow[i4];
        acc += a.x * w.x + a.y * w.y + a.z * w.z + a.w * w.w;
    }
    #pragma unroll
    for (int o = 16; o; o >>= 1) acc += __shfl_xor_sync(0xffffffffu, acc, o);
    if (lane == 0) g_oattn[b * Ee + j] = acc + vb[j];
}

// ---------------- out = out_attn @ out_w.T + out_b ----------------
__global__ __launch_bounds__(256) void oproj_kernel(const float* __restrict__ ow,
                                                    const float* __restrict__ ob,
                                                    float* __restrict__ out) {
    int b = blockIdx.y;
    int warp = threadIdx.x >> 5, lane = threadIdx.x & 31;
    int j = blockIdx.x * 8 + warp;
    const float4* arow = reinterpret_cast<const float4*>(g_oattn + (size_t)b * Ee);
    const float4* wrow = reinterpret_cast<const float4*>(ow + (size_t)j * Ee);
    float acc = 0.f;
    #pragma unroll
    for (int it = 0; it < 16; it++) {
        int i4 = it * 32 + lane;
        float4 a = arow[i4], w = wrow[i4];
        acc += a.x * w.x + a.y * w.y + a.z * w.z + a.w * w.w;
    }
    #pragma unroll
    for (int o = 16; o; o >>= 1) acc += __shfl_xor_sync(0xffffffffu, acc, o);
    if (lane == 0) out[b * Ee + j] = acc + ob[j];
}

// ---------------- launch ----------------
extern "C" void kernel_launch(void* const* d_in, const int* in_sizes, int n_in,
                              void* d_out, int out_size) {
    const float* hs_in = (const float*)d_in[0];
    const int*   ids   = (const int*)d_in[1];
    const float* lnw = (const float*)d_in[2];
    const float* lnb = (const float*)d_in[3];
    const float* qw  = (const float*)d_in[4];
    const float* qb  = (const float*)d_in[5];
    const float* kw  = (const float*)d_in[6];
    const float* kb  = (const float*)d_in[7];
    const float* vw  = (const float*)d_in[8];
    const float* vb  = (const float*)d_in[9];
    const float* ow  = (const float*)d_in[10];
    const float* ob  = (const float*)d_in[11];
    float* out = (float*)d_out;

    cudaFuncSetAttribute(gemm_scores, cudaFuncAttributeMaxDynamicSharedMemorySize, GEMM_SMEM);

    ln_kernel<<<Bb * Ss, 256>>>(hs_in, lnw, lnb);
    ix_kernel<<<Bb, 256>>>(ids);
    qpmat_kernel<<<dim3(Hh, Bb), 256>>>(qw, qb, kw);
    gemm_scores<<<dim3(Bb * Hh, Ss / 64), 256, GEMM_SMEM>>>(kb);
    softmax_kernel<<<Bb * Hh, 256>>>();
    zero_c_kernel<<<(Bb * Hh * Ee + 255) / 256, 256>>>();
    cvec_kernel<<<dim3(Ee / 128, Bb, 8), 128>>>();
    vproj_kernel<<<dim3(Ee / 8, Bb), 256>>>(vw, vb);
    oproj_kernel<<<dim3(Ee / 8, Bb), 256>>>(ow, ob, out);
}

// round 11
// speedup vs baseline: 1.3587x; 1.3587x over previous
#include <cuda_runtime.h>
#include <cuda_fp16.h>
#include <cstdint>
#include <math.h>

#define Bb 8
#define Ss 2048
#define Ee 2048
#define Hh 16
#define Dd 128
#define PADTOK 50257

// ---------------- scratch (device globals: allocation-free) ----------------
__device__ __half g_hsH[(size_t)Bb * Ss * Ee];      // hi fp16 split of LN output
__device__ __half g_hsL[(size_t)Bb * Ss * Ee];      // lo fp16 split
__device__ __half g_pH[(size_t)Bb * Hh * 64 * Ee];  // projected weights fp16 (cos/sin coeffs)
__device__ float  g_pF[(size_t)Bb * Hh * 64 * Ee];  // projected weights fp32 (for refine)
__device__ float g_Cv[(size_t)Bb * Hh * Ee];        // C vector per (b,h), fp32
__device__ float g_q[Bb * Ee];
__device__ float g_sc[Bb * Hh * Ss];
__device__ float g_c[Bb * Hh * Ee];
__device__ float g_oattn[Bb * Ee];
__device__ int   g_ix[Bb];

// ---------------- helpers ----------------
__device__ __forceinline__ void splitp_h(float f0, float f1, uint32_t& hi, uint32_t& lo) {
    __half2 Hv = __floats2half2_rn(f0, f1);
    float r0 = f0 - __low2float(Hv);
    float r1 = f1 - __high2float(Hv);
    __half2 Lv = __floats2half2_rn(r0, r1);
    hi = *reinterpret_cast<uint32_t*>(&Hv);
    lo = *reinterpret_cast<uint32_t*>(&Lv);
}

__device__ __forceinline__ float h2sum(uint32_t h, uint32_t l, int sel) {
    __half2 hv = *reinterpret_cast<__half2*>(&h);
    __half2 lv = *reinterpret_cast<__half2*>(&l);
    return sel ? (__high2float(hv) + __high2float(lv))
               : (__low2float(hv) + __low2float(lv));
}

// ---------------- LayerNorm + fp16 hi/lo split ----------------
__global__ __launch_bounds__(256) void ln_kernel(const float* __restrict__ x,
                                                 const float* __restrict__ w,
                                                 const float* __restrict__ bias) {
    int row = blockIdx.x;
    const float4* xin = reinterpret_cast<const float4*>(x + (size_t)row * Ee);
    int tid = threadIdx.x;
    float4 v0 = xin[tid];
    float4 v1 = xin[tid + 256];
    float s  = v0.x + v0.y + v0.z + v0.w + v1.x + v1.y + v1.z + v1.w;
    float s2 = v0.x*v0.x + v0.y*v0.y + v0.z*v0.z + v0.w*v0.w
             + v1.x*v1.x + v1.y*v1.y + v1.z*v1.z + v1.w*v1.w;
    #pragma unroll
    for (int o = 16; o; o >>= 1) {
        s  += __shfl_xor_sync(0xffffffffu, s, o);
        s2 += __shfl_xor_sync(0xffffffffu, s2, o);
    }
    __shared__ float red[16];
    __shared__ float mv[2];
    int warp = tid >> 5, lane = tid & 31;
    if (lane == 0) { red[warp] = s; red[warp + 8] = s2; }
    __syncthreads();
    if (tid == 0) {
        float a = 0.f, b2 = 0.f;
        #pragma unroll
        for (int i = 0; i < 8; i++) { a += red[i]; b2 += red[i + 8]; }
        float mu  = a / (float)Ee;
        float var = b2 / (float)Ee - mu * mu;
        mv[0] = mu; mv[1] = rsqrtf(var + 1e-5f);
    }
    __syncthreads();
    float mu = mv[0], rs = mv[1];
    const float4* wv4 = reinterpret_cast<const float4*>(w);
    const float4* bv4 = reinterpret_cast<const float4*>(bias);
    uint2* outH = reinterpret_cast<uint2*>(g_hsH + (size_t)row * Ee);
    uint2* outL = reinterpret_cast<uint2*>(g_hsL + (size_t)row * Ee);
    {
        float4 wv = wv4[tid], bv = bv4[tid], o;
        o.x = (v0.x - mu) * rs * wv.x + bv.x;
        o.y = (v0.y - mu) * rs * wv.y + bv.y;
        o.z = (v0.z - mu) * rs * wv.z + bv.z;
        o.w = (v0.w - mu) * rs * wv.w + bv.w;
        uint32_t h0, l0, h1, l1;
        splitp_h(o.x, o.y, h0, l0); splitp_h(o.z, o.w, h1, l1);
        outH[tid] = make_uint2(h0, h1);
        outL[tid] = make_uint2(l0, l1);
    }
    {
        float4 wv = wv4[tid + 256], bv = bv4[tid + 256], o;
        o.x = (v1.x - mu) * rs * wv.x + bv.x;
        o.y = (v1.y - mu) * rs * wv.y + bv.y;
        o.z = (v1.z - mu) * rs * wv.z + bv.z;
        o.w = (v1.w - mu) * rs * wv.w + bv.w;
        uint32_t h0, l0, h1, l1;
        splitp_h(o.x, o.y, h0, l0); splitp_h(o.z, o.w, h1, l1);
        outH[tid + 256] = make_uint2(h0, h1);
        outL[tid + 256] = make_uint2(l0, l1);
    }
}

// ---------------- last non-pad index ----------------
__global__ __launch_bounds__(256) void ix_kernel(const int* __restrict__ ids) {
    int b = blockIdx.x;
    int m = -1;
    for (int s = threadIdx.x; s < Ss; s += 256)
        if (ids[b * Ss + s] != PADTOK) m = s;
    #pragma unroll
    for (int o = 16; o; o >>= 1) m = max(m, __shfl_xor_sync(0xffffffffu, m, o));
    __shared__ int rm[8];
    int warp = threadIdx.x >> 5, lane = threadIdx.x & 31;
    if (lane == 0) rm[warp] = m;
    __syncthreads();
    if (threadIdx.x == 0) {
        int mm = -1;
        #pragma unroll
        for (int i = 0; i < 8; i++) mm = max(mm, rm[i]);
        g_ix[b] = (mm < 0) ? 0 : mm;
    }
}

// ---------------- fused q + P-matrix kernel (per (h, b) block) ----------------
__global__ __launch_bounds__(256) void qpmat_kernel(const float* __restrict__ qw,
                                                    const float* __restrict__ qb,
                                                    const float* __restrict__ kw) {
    __shared__ float qs[128];
    const int tid = threadIdx.x, warp = tid >> 5, lane = tid & 31;
    const int h = blockIdx.x, b = blockIdx.y;

    size_t hb = ((size_t)(b * Ss) + g_ix[b]) * Ee;
    const uint2* hH = reinterpret_cast<const uint2*>(g_hsH + hb);
    const uint2* hL = reinterpret_cast<const uint2*>(g_hsL + hb);

    for (int rr = 0; rr < 16; rr++) {
        int d = warp * 16 + rr;
        int j = h * 128 + d;
        const float4* wrow = reinterpret_cast<const float4*>(qw + (size_t)j * Ee);
        float acc = 0.f;
        #pragma unroll
        for (int it = 0; it < 16; it++) {
            int i4 = it * 32 + lane;
            uint2 hv = hH[i4], lv = hL[i4];
            float4 w = wrow[i4];
            acc += h2sum(hv.x, lv.x, 0) * w.x;
            acc += h2sum(hv.x, lv.x, 1) * w.y;
            acc += h2sum(hv.y, lv.y, 0) * w.z;
            acc += h2sum(hv.y, lv.y, 1) * w.w;
        }
        #pragma unroll
        for (int o = 16; o; o >>= 1) acc += __shfl_xor_sync(0xffffffffu, acc, o);
        if (lane == 0) {
            float v = acc + qb[j];
            qs[d] = v;
            g_q[b * Ee + j] = v;
        }
    }
    __syncthreads();

    #pragma unroll
    for (int i = 0; i < 8; i++) {
        int e = tid + 256 * i;
        size_t pbase = ((size_t)(b * Hh + h)) * 64 * Ee + e;
        const float* kwb = kw + (size_t)h * Dd * Ee + e;
        #pragma unroll 4
        for (int j = 0; j < 32; j++) {
            float k0 = kwb[(size_t)(2 * j) * Ee];
            float k1 = kwb[(size_t)(2 * j + 1) * Ee];
            float A  = k0 * qs[2 * j]     + k1 * qs[2 * j + 1];
            float Bv = k0 * qs[2 * j + 1] - k1 * qs[2 * j];
            g_pH[pbase + (size_t)j * Ee] = __float2half_rn(A);
            g_pH[pbase + (size_t)(32 + j) * Ee] = __float2half_rn(Bv);
            g_pF[pbase + (size_t)j * Ee] = A;
            g_pF[pbase + (size_t)(32 + j) * Ee] = Bv;
        }
        float C = 0.f;
        #pragma unroll 8
        for (int d = 64; d < 128; d++) C += kwb[(size_t)d * Ee] * qs[d];
        g_Cv[(size_t)(b * Hh + h) * Ee + e] = C;
    }
}

// ---------------- GEMM G = hs @ P^T (2-term fp16: A split hi/lo, B single) -----
__device__ __forceinline__ void mma_f16(float c[4], uint32_t a0, uint32_t a1, uint32_t a2,
                                        uint32_t a3, uint32_t b0, uint32_t b1) {
    asm volatile(
        "mma.sync.aligned.m16n8k16.row.col.f32.f16.f16.f32 "
        "{%0,%1,%2,%3}, {%4,%5,%6,%7}, {%8,%9}, {%0,%1,%2,%3};"
        : "+f"(c[0]), "+f"(c[1]), "+f"(c[2]), "+f"(c[3])
        : "r"(a0), "r"(a1), "r"(a2), "r"(a3), "r"(b0), "r"(b1));
}

__device__ __forceinline__ void ldsm4(uint32_t r[4], uint32_t a) {
    asm volatile("ldmatrix.sync.aligned.m8n8.x4.shared.b16 {%0,%1,%2,%3}, [%4];"
                 : "=r"(r[0]), "=r"(r[1]), "=r"(r[2]), "=r"(r[3]) : "r"(a));
}

__device__ __forceinline__ void cp16(uint32_t dst, const void* src) {
    asm volatile("cp.async.cg.shared.global [%0], [%1], 16;" :: "r"(dst), "l"(src) : "memory");
}
#define CP_COMMIT() asm volatile("cp.async.commit_group;" ::: "memory")
#define CP_WAIT1()  asm volatile("cp.async.wait_group 1;" ::: "memory")
#define CP_WAIT0()  asm volatile("cp.async.wait_group 0;" ::: "memory")

// stage layout: A 128x128B per limb, B_H 64x128B
#define GA_H 0
#define GA_L 16384
#define GB_H 32768
#define GM_STAGE 40960
#define GEMM_SMEM (2 * GM_STAGE)   // 80 KB

__global__ void __launch_bounds__(256, 2) gemm_scores(const float* __restrict__ kb) {
    extern __shared__ char dsm[];
    __shared__ __align__(16) float pbA[32], pbB[32], pbCs[4];
    __shared__ __align__(16) double finv[32];
    __shared__ __align__(16) float Cs[2048];
    __shared__ __align__(16) float cred[128][2];

    const int tid = threadIdx.x, warp = tid >> 5, lane = tid & 31;
    const int bh = blockIdx.x, b = bh >> 4, h = bh & 15;   // bh fast: L2 A-sharing
    const int s0 = blockIdx.y * 128;

    if (tid < 32) {
        finv[tid] = exp(-((double)(2 * tid) / 64.0) * 9.210340371976184);
        float q0 = g_q[b * Ee + h * Dd + 2 * tid];
        float q1 = g_q[b * Ee + h * Dd + 2 * tid + 1];
        float k0 = kb[h * Dd + 2 * tid];
        float k1 = kb[h * Dd + 2 * tid + 1];
        pbA[tid] = q0 * k0 + q1 * k1;
        pbB[tid] = q1 * k0 - q0 * k1;
    } else if (tid == 32) {
        float a = 0.f;
        for (int d = 64; d < 128; d++) a += kb[h * Dd + d] * g_q[b * Ee + h * Dd + d];
        pbCs[0] = a;
    }
    {
        const float4* cv = reinterpret_cast<const float4*>(g_Cv + (size_t)bh * Ee);
        #pragma unroll
        for (int i = 0; i < 2; i++) {
            float4 v = cv[tid + i * 256];
            *reinterpret_cast<float4*>(&Cs[(tid + i * 256) * 4]) = v;
        }
    }

    uint32_t sb;
    asm("{ .reg .u64 t; cvta.to.shared.u64 t, %1; cvt.u32.u64 %0, t; }" : "=r"(sb) : "l"(dsm));

    const char* aHb = (const char*)(g_hsH + (size_t)(b * Ss + s0) * Ee);
    const char* aLb = (const char*)(g_hsL + (size_t)(b * Ss + s0) * Ee);
    const char* pHb = (const char*)(g_pH + (size_t)bh * 64 * Ee);

// 2560 cp16 per stage: A_H 0..1023, A_L 1024..2047, B_H 2048..2559
#define G_LOAD_STAGE(st, k0w)                                                     \
    {                                                                             \
        uint32_t sbase = sb + (st) * GM_STAGE;                                    \
        _Pragma("unroll")                                                         \
        for (int i = 0; i < 10; i++) {                                            \
            int id = tid + 256 * i;                                               \
            int arr = (id < 1024) ? 0 : (id < 2048) ? 1 : 2;                      \
            int rid = id - ((arr == 0) ? 0 : (arr == 1) ? 1024 : 2048);           \
            int row = rid >> 3, c = rid & 7;                                      \
            uint32_t aoff = (arr == 0) ? GA_H : (arr == 1) ? GA_L : GB_H;         \
            const char* src = (arr == 0) ? aHb : (arr == 1) ? aLb : pHb;          \
            uint32_t dst = sbase + aoff +                                         \
                (uint32_t)(row * 128 + ((c ^ (row & 7)) << 4));                   \
            cp16(dst, src + (size_t)row * 4096 + (size_t)(k0w) * 2 + c * 16);     \
        }                                                                         \
        CP_COMMIT();                                                              \
    }

    float acc[2][4][4];
    #pragma unroll
    for (int i = 0; i < 2; i++)
        #pragma unroll
        for (int j = 0; j < 4; j++)
            #pragma unroll
            for (int k = 0; k < 4; k++) acc[i][j][k] = 0.f;
    float cacc[2][2] = {{0.f, 0.f}, {0.f, 0.f}};

    const int warpM = warp >> 1, warpN = warp & 1;
    const int rA = warpM * 32, nbase = warpN * 32;
    const int g = lane >> 2, tq = lane & 3;

    G_LOAD_STAGE(0, 0);

    for (int k = 0; k < 32; k++) {
        const int s = k & 1;
        const int k0w = k * 64;
        if (k + 1 < 32) { G_LOAD_STAGE(s ^ 1, (k + 1) * 64); CP_WAIT1(); }
        else            { CP_WAIT0(); }
        __syncthreads();
        uint32_t base = sb + s * GM_STAGE;

        #pragma unroll
        for (int kk = 0; kk < 4; kk++) {
            const int kkc = kk * 2;
            uint32_t aH[2][4], aL[2][4];
            #pragma unroll
            for (int mt = 0; mt < 2; mt++) {
                int row = rA + mt * 16 + (lane & 15);
                int c16 = kkc + (lane >> 4);
                uint32_t off = (uint32_t)(row * 128 + ((c16 ^ (row & 7)) << 4));
                ldsm4(aH[mt], base + GA_H + off);
                ldsm4(aL[mt], base + GA_L + off);
            }
            uint32_t bH[8];
            #pragma unroll
            for (int tp = 0; tp < 2; tp++) {
                int row = nbase + tp * 16 + ((lane >> 4) << 3) + (lane & 7);
                int c16 = kkc + ((lane >> 3) & 1);
                uint32_t off = (uint32_t)(row * 128 + ((c16 ^ (row & 7)) << 4));
                ldsm4(&bH[tp * 4], base + GB_H + off);
            }
            // in-register C-dot on the fma pipe (wn0: kk 0-1, wn1: kk 2-3)
            if ((kk >> 1) == warpN) {
                #pragma unroll
                for (int mt = 0; mt < 2; mt++) {
                    #pragma unroll
                    for (int r = 0; r < 4; r++) {
                        float2 fh = __half22float2(*reinterpret_cast<__half2*>(&aH[mt][r]));
                        float2 fl = __half22float2(*reinterpret_cast<__half2*>(&aL[mt][r]));
                        int ki = k0w + kk * 16 + tq * 2 + ((r & 2) ? 8 : 0);
                        cacc[mt][r & 1] += (fh.x + fl.x) * Cs[ki] + (fh.y + fl.y) * Cs[ki + 1];
                    }
                }
            }
            #pragma unroll
            for (int nt = 0; nt < 4; nt++) {
                #pragma unroll
                for (int mt = 0; mt < 2; mt++) {
                    mma_f16(acc[mt][nt], aH[mt][0], aH[mt][1], aH[mt][2], aH[mt][3],
                            bH[nt * 2], bH[nt * 2 + 1]);
                    mma_f16(acc[mt][nt], aL[mt][0], aL[mt][1], aL[mt][2], aL[mt][3],
                            bH[nt * 2], bH[nt * 2 + 1]);
                }
            }
        }
        __syncthreads();
    }

    #pragma unroll
    for (int mt = 0; mt < 2; mt++) {
        #pragma unroll
        for (int rr = 0; rr < 2; rr++) {
            float p = cacc[mt][rr];
            p += __shfl_xor_sync(0xffffffffu, p, 1);
            p += __shfl_xor_sync(0xffffffffu, p, 2);
            if (tq == 0) cred[rA + mt * 16 + rr * 8 + g][warpN] = p;
        }
    }

    float* Gs = reinterpret_cast<float*>(dsm);   // [128][65]
    #pragma unroll
    for (int nt = 0; nt < 4; nt++) {
        #pragma unroll
        for (int mt = 0; mt < 2; mt++) {
            int r = rA + mt * 16 + (lane >> 2);
            int n = nbase + nt * 8 + 2 * (lane & 3);
            float* g0 = Gs + r * 65 + n;
            g0[0] = acc[mt][nt][0];
            g0[1] = acc[mt][nt][1];
            g0[65 * 8] = acc[mt][nt][2];
            g0[65 * 8 + 1] = acc[mt][nt][3];
        }
    }
    __syncthreads();
    if (tid < 128) {
        const double INV2PI = 0.15915494309189535;
        const double TWOPI  = 6.283185307179586;
        int s = s0 + tid;
        const float* row = Gs + tid * 65;
        float accS = cred[tid][0] + cred[tid][1] + pbCs[0];
        #pragma unroll 8
        for (int j = 0; j < 32; j++) {
            double ang = (double)s * finv[j];
            double kq = rint(ang * INV2PI);
            float r = (float)(ang - kq * TWOPI);
            float sn, cs;
            __sincosf(r, &sn, &cs);
            accS += cs * (row[j] + pbA[j]) + sn * (row[32 + j] + pbB[j]);
        }
        g_sc[(size_t)bh * Ss + s] = accS;
    }
}

// ---------------- fused top-32 exact refinement + softmax (per b,h) ----------------
// smem floats: sc 2048 | msk 2048 | Pc 64*261 | Hc 32*261 | Cc 261 | G 32*68
#define SRP 261
#define SR_SC   0
#define SR_MSK  2048
#define SR_PC   4096
#define SR_HC   (SR_PC + 64 * SRP)
#define SR_CC   (SR_HC + 32 * SRP)
#define SR_G    (SR_CC + SRP)
#define SR_TOT  (SR_G + 32 * 68)
#define SR_SMEM (SR_TOT * 4)

__global__ void __launch_bounds__(256, 1) softmax_refine(const float* __restrict__ kb) {
    extern __shared__ float sm[];
    float* sc  = sm + SR_SC;
    float* msk = sm + SR_MSK;
    float* Pc  = sm + SR_PC;
    float* Hc  = sm + SR_HC;
    float* Cc  = sm + SR_CC;
    float* G   = sm + SR_G;
    __shared__ float pbA[32], pbB[32], pbCs[1];
    __shared__ double finv[32];
    __shared__ int topidx[32];
    __shared__ float redv[8];
    __shared__ int   redi[8];

    const int tid = threadIdx.x, warp = tid >> 5, lane = tid & 31;
    const int bh = blockIdx.x, b = bh >> 4, h = bh & 15;

    // phase 1: load scores + constants
    #pragma unroll
    for (int i = 0; i < 8; i++) {
        float v = g_sc[(size_t)bh * Ss + tid + i * 256];
        sc[tid + i * 256] = v;
        msk[tid + i * 256] = v;
    }
    if (tid < 32) {
        finv[tid] = exp(-((double)(2 * tid) / 64.0) * 9.210340371976184);
        float q0 = g_q[b * Ee + h * Dd + 2 * tid];
        float q1 = g_q[b * Ee + h * Dd + 2 * tid + 1];
        float k0 = kb[h * Dd + 2 * tid];
        float k1 = kb[h * Dd + 2 * tid + 1];
        pbA[tid] = q0 * k0 + q1 * k1;
        pbB[tid] = q1 * k0 - q0 * k1;
    } else if (tid == 32) {
        float a = 0.f;
        for (int d = 64; d < 128; d++) a += kb[h * Dd + d] * g_q[b * Ee + h * Dd + d];
        pbCs[0] = a;
    }
    __syncthreads();

    // phase 2: top-32 selection (iterative argmax)
    for (int it = 0; it < 32; it++) {
        float bv = -3e38f; int bi = 0;
        #pragma unroll
        for (int i = 0; i < 8; i++) {
            int idx = tid + i * 256;
            float v = msk[idx];
            if (v > bv) { bv = v; bi = idx; }
        }
        #pragma unroll
        for (int o = 16; o; o >>= 1) {
            float ov = __shfl_xor_sync(0xffffffffu, bv, o);
            int   oi = __shfl_xor_sync(0xffffffffu, bi, o);
            if (ov > bv || (ov == bv && oi < bi)) { bv = ov; bi = oi; }
        }
        if (lane == 0) { redv[warp] = bv; redi[warp] = bi; }
        __syncthreads();
        if (tid == 0) {
            float best = redv[0]; int besti = redi[0];
            #pragma unroll
            for (int i = 1; i < 8; i++)
                if (redv[i] > best || (redv[i] == best && redi[i] < besti)) {
                    best = redv[i]; besti = redi[i];
                }
            topidx[it] = besti;
            msk[besti] = -3e38f;
        }
        __syncthreads();
    }

    // phase 3-4: exact G accumulation, k-chunked
    float acc16[4][4];
    #pragma unroll
    for (int u = 0; u < 4; u++)
        #pragma unroll
        for (int v = 0; v < 4; v++) acc16[u][v] = 0.f;
    float Cacc = 0.f;
    const int kq = tid >> 7, rest = tid & 127;
    const int tg = rest >> 4, jg = rest & 15;

    for (int kc = 0; kc < 8; kc++) {
        __syncthreads();
        // load Pc: 64 rows x 256 cols
        #pragma unroll
        for (int it = 0; it < 64; it++) {
            int flat = tid + 256 * it;
            int j = flat >> 8, i = flat & 255;
            Pc[j * SRP + i] = g_pF[((size_t)bh * 64 + j) * Ee + kc * 256 + i];
        }
        // load Hc: 32 tokens x 256 cols (fp32 = hsH + hsL)
        #pragma unroll
        for (int it = 0; it < 32; it++) {
            int flat = tid + 256 * it;
            int t = flat >> 8, i = flat & 255;
            size_t base = ((size_t)(b * Ss) + topidx[t]) * Ee + kc * 256 + i;
            Hc[t * SRP + i] = __half2float(g_hsH[base]) + __half2float(g_hsL[base]);
        }
        Cc[tid] = g_Cv[(size_t)bh * Ee + kc * 256 + tid];
        __syncthreads();

        #pragma unroll 4
        for (int ii = 0; ii < 128; ii++) {
            int kl = kq * 128 + ii;
            float pv[4], hv[4];
            #pragma unroll
            for (int u = 0; u < 4; u++) pv[u] = Pc[(jg + 16 * u) * SRP + kl];
            #pragma unroll
            for (int v = 0; v < 4; v++) hv[v] = Hc[(tg * 4 + v) * SRP + kl];
            #pragma unroll
            for (int u = 0; u < 4; u++)
                #pragma unroll
                for (int v = 0; v < 4; v++) acc16[u][v] += pv[u] * hv[v];
        }
        if (tid < 64) {
            int tC = tid >> 1, kqC = tid & 1;
            #pragma unroll 4
            for (int ii = 0; ii < 128; ii++)
                Cacc += Hc[tC * SRP + kqC * 128 + ii] * Cc[kqC * 128 + ii];
        }
    }

    // phase 5: reduce kq halves into G
    __syncthreads();
    if (kq == 0) {
        #pragma unroll
        for (int u = 0; u < 4; u++)
            #pragma unroll
            for (int v = 0; v < 4; v++)
                G[(tg * 4 + v) * 68 + jg + 16 * u] = acc16[u][v];
        if (tid < 64) G[(tid >> 1) * 68 + 64 + (tid & 1)] = Cacc;
    }
    __syncthreads();
    if (kq == 1) {
        #pragma unroll
        for (int u = 0; u < 4; u++)
            #pragma unroll
            for (int v = 0; v < 4; v++)
                G[(tg * 4 + v) * 68 + jg + 16 * u] += acc16[u][v];
    }
    __syncthreads();

    // phase 6: exact logits for the 32 tokens
    {
        const double INV2PI = 0.15915494309189535;
        const double TWOPI  = 6.283185307179586;
        #pragma unroll
        for (int tt = 0; tt < 4; tt++) {
            int t = warp * 4 + tt;
            int s = topidx[t];
            double ang = (double)s * finv[lane];
            double kqd = rint(ang * INV2PI);
            float r = (float)(ang - kqd * TWOPI);
            float sn, cs;
            __sincosf(r, &sn, &cs);
            float val = cs * (G[t * 68 + lane] + pbA[lane])
                      + sn * (G[t * 68 + 32 + lane] + pbB[lane]);
            if (lane == 0) val += G[t * 68 + 64] + G[t * 68 + 65] + pbCs[0];
            #pragma unroll
            for (int o = 16; o; o >>= 1) val += __shfl_xor_sync(0xffffffffu, val, o);
            if (lane == 0) sc[s] = val;
        }
    }
    __syncthreads();

    // phase 7: softmax over sc, write probs
    float v[8];
    float m = -3e38f;
    #pragma unroll
    for (int i = 0; i < 8; i++) { v[i] = sc[tid + i * 256]; m = fmaxf(m, v[i]); }
    #pragma unroll
    for (int o = 16; o; o >>= 1) m = fmaxf(m, __shfl_xor_sync(0xffffffffu, m, o));
    if (lane == 0) redv[warp] = m;
    __syncthreads();
    float mm = redv[0];
    #pragma unroll
    for (int i = 1; i < 8; i++) mm = fmaxf(mm, redv[i]);
    float ssum = 0.f;
    #pragma unroll
    for (int i = 0; i < 8; i++) { v[i] = expf(v[i] - mm); ssum += v[i]; }
    #pragma unroll
    for (int o = 16; o; o >>= 1) ssum += __shfl_xor_sync(0xffffffffu, ssum, o);
    __syncthreads();
    if (lane == 0) redv[warp] = ssum;
    __syncthreads();
    float tot = 0.f;
    #pragma unroll
    for (int i = 0; i < 8; i++) tot += redv[i];
    float inv = 1.f / tot;
    #pragma unroll
    for (int i = 0; i < 8; i++) g_sc[(size_t)bh * Ss + tid + i * 256] = v[i] * inv;
}

// ---------------- c[b,h,e] = sum_s attn * hs ----------------
__global__ void zero_c_kernel() {
    int i = blockIdx.x * blockDim.x + threadIdx.x;
    if (i < Bb * Hh * Ee) g_c[i] = 0.f;
}

__global__ __launch_bounds__(128) void cvec_kernel() {
    __shared__ float at[16][128];
    int tid = threadIdx.x;
    int b = blockIdx.y;
    int e = blockIdx.x * 128 + tid;
    int sbase = blockIdx.z * 256;
    float acc[16];
    #pragma unroll
    for (int i = 0; i < 16; i++) acc[i] = 0.f;
    for (int sc = 0; sc < 256; sc += 128) {
        #pragma unroll
        for (int i = 0; i < 16; i++) {
            int idx = tid + i * 128;
            int hh = idx >> 7, si = idx & 127;
            at[hh][si] = g_sc[(size_t)(b * Hh + hh) * Ss + sbase + sc + si];
        }
        __syncthreads();
        size_t base = (size_t)(b * Ss + sbase + sc) * Ee + e;
        #pragma unroll 4
        for (int si = 0; si < 128; si++) {
            float x = __half2float(g_hsH[base + (size_t)si * Ee])
                    + __half2float(g_hsL[base + (size_t)si * Ee]);
            #pragma unroll
            for (int hh = 0; hh < 16; hh++) acc[hh] += at[hh][si] * x;
        }
        __syncthreads();
    }
    #pragma unroll
    for (int hh = 0; hh < 16; hh++)
        atomicAdd(&g_c[(size_t)(b * Hh + hh) * Ee + e], acc[hh]);
}

// ---------------- out_attn = c @ v_w.T (per head) + v_b ----------------
__global__ __launch_bounds__(256) void vproj_kernel(const float* __restrict__ vw,
                                                    const float* __restrict__ vb) {
    int b = blockIdx.y;
    int warp = threadIdx.x >> 5, lane = threadIdx.x & 31;
    int j = blockIdx.x * 8 + warp;
    int hh = j >> 7;
    const float4* crow = reinterpret_cast<const float4*>(g_c + (size_t)(b * Hh + hh) * Ee);
    const float4* wrow = reinterpret_cast<const float4*>(vw + (size_t)j * Ee);
    float acc = 0.f;
    #pragma unroll
    for (int it = 0; it < 16; it++) {
        int i4 = it * 32 + lane;
        float4 a = crow[i4], w = wrow[i4];
        acc += a.x * w.x + a.y * w.y + a.z * w.z + a.w * w.w;
    }
    #pragma unroll
    for (int o = 16; o; o >>= 1) acc += __shfl_xor_sync(0xffffffffu, acc, o);
    if (lane == 0) g_oattn[b * Ee + j] = acc + vb[j];
}

// ---------------- out = out_attn @ out_w.T + out_b ----------------
__global__ __launch_bounds__(256) void oproj_kernel(const float* __restrict__ ow,
                                                    const float* __restrict__ ob,
                                                    float* __restrict__ out) {
    int b = blockIdx.y;
    int warp = threadIdx.x >> 5, lane = threadIdx.x & 31;
    int j = blockIdx.x * 8 + warp;
    const float4* arow = reinterpret_cast<const float4*>(g_oattn + (size_t)b * Ee);
    const float4* wrow = reinterpret_cast<const float4*>(ow + (size_t)j * Ee);
    float acc = 0.f;
    #pragma unroll
    for (int it = 0; it < 16; it++) {
        int i4 = it * 32 + lane;
        float4 a = arow[i4], w = wrow[i4];
        acc += a.x * w.x + a.y * w.y + a.z * w.z + a.w * w.w;
    }
    #pragma unroll
    for (int o = 16; o; o >>= 1) acc += __shfl_xor_sync(0xffffffffu, acc, o);
    if (lane == 0) out[b * Ee + j] = acc + ob[j];
}

// ---------------- launch ----------------
extern "C" void kernel_launch(void* const* d_in, const int* in_sizes, int n_in,
                              void* d_out, int out_size) {
    const float* hs_in = (const float*)d_in[0];
    const int*   ids   = (const int*)d_in[1];
    const float* lnw = (const float*)d_in[2];
    const float* lnb = (const float*)d_in[3];
    const float* qw  = (const float*)d_in[4];
    const float* qb  = (const float*)d_in[5];
    const float* kw  = (const float*)d_in[6];
    const float* kb  = (const float*)d_in[7];
    const float* vw  = (const float*)d_in[8];
    const float* vb  = (const float*)d_in[9];
    const float* ow  = (const float*)d_in[10];
    const float* ob  = (const float*)d_in[11];
    float* out = (float*)d_out;

    cudaFuncSetAttribute(gemm_scores, cudaFuncAttributeMaxDynamicSharedMemorySize, GEMM_SMEM);
    cudaFuncSetAttribute(softmax_refine, cudaFuncAttributeMaxDynamicSharedMemorySize, SR_SMEM);

    ln_kernel<<<Bb * Ss, 256>>>(hs_in, lnw, lnb);
    ix_kernel<<<Bb, 256>>>(ids);
    qpmat_kernel<<<dim3(Hh, Bb), 256>>>(qw, qb, kw);
    gemm_scores<<<dim3(Bb * Hh, Ss / 128), 256, GEMM_SMEM>>>(kb);
    softmax_refine<<<Bb * Hh, 256, SR_SMEM>>>(kb);
    zero_c_kernel<<<(Bb * Hh * Ee + 255) / 256, 256>>>();
    cvec_kernel<<<dim3(Ee / 128, Bb, 8), 128>>>();
    vproj_kernel<<<dim3(Ee / 8, Bb), 256>>>(vw, vb);
    oproj_kernel<<<dim3(Ee / 8, Bb), 256>>>(ow, ob, out);
}

// round 12
// speedup vs baseline: 1.4883x; 1.0954x over previous
#include <cuda_runtime.h>
#include <cuda_fp16.h>
#include <cstdint>
#include <math.h>

#define Bb 8
#define Ss 2048
#define Ee 2048
#define Hh 16
#define Dd 128
#define PADTOK 50257

// ---------------- scratch (device globals: allocation-free) ----------------
__device__ __half g_hsH[(size_t)Bb * Ss * Ee];      // hi fp16 split of LN output
__device__ __half g_hsL[(size_t)Bb * Ss * Ee];      // lo fp16 split
__device__ __half g_pH[(size_t)Bb * Hh * 64 * Ee];  // projected weights fp16 (cos/sin coeffs)
__device__ float  g_pF[(size_t)Bb * Hh * 64 * Ee];  // projected weights fp32 (for refine)
__device__ float g_Cv[(size_t)Bb * Hh * Ee];        // C vector per (b,h), fp32
__device__ float g_q[Bb * Ee];
__device__ float g_sc[Bb * Hh * Ss];
__device__ float g_c[Bb * Hh * Ee];
__device__ float g_oattn[Bb * Ee];
__device__ int   g_ix[Bb];
__device__ int   g_top[Bb * Hh * 32];               // top-32 indices per bh
__device__ float g_Gp[(size_t)Bb * Hh * 8 * 32 * 68];  // partial G tiles (bh, kc)

// ---------------- helpers ----------------
__device__ __forceinline__ void splitp_h(float f0, float f1, uint32_t& hi, uint32_t& lo) {
    __half2 Hv = __floats2half2_rn(f0, f1);
    float r0 = f0 - __low2float(Hv);
    float r1 = f1 - __high2float(Hv);
    __half2 Lv = __floats2half2_rn(r0, r1);
    hi = *reinterpret_cast<uint32_t*>(&Hv);
    lo = *reinterpret_cast<uint32_t*>(&Lv);
}

__device__ __forceinline__ float h2sum(uint32_t h, uint32_t l, int sel) {
    __half2 hv = *reinterpret_cast<__half2*>(&h);
    __half2 lv = *reinterpret_cast<__half2*>(&l);
    return sel ? (__high2float(hv) + __high2float(lv))
               : (__low2float(hv) + __low2float(lv));
}

// ---------------- LayerNorm + fp16 hi/lo split ----------------
__global__ __launch_bounds__(256) void ln_kernel(const float* __restrict__ x,
                                                 const float* __restrict__ w,
                                                 const float* __restrict__ bias) {
    int row = blockIdx.x;
    const float4* xin = reinterpret_cast<const float4*>(x + (size_t)row * Ee);
    int tid = threadIdx.x;
    float4 v0 = xin[tid];
    float4 v1 = xin[tid + 256];
    float s  = v0.x + v0.y + v0.z + v0.w + v1.x + v1.y + v1.z + v1.w;
    float s2 = v0.x*v0.x + v0.y*v0.y + v0.z*v0.z + v0.w*v0.w
             + v1.x*v1.x + v1.y*v1.y + v1.z*v1.z + v1.w*v1.w;
    #pragma unroll
    for (int o = 16; o; o >>= 1) {
        s  += __shfl_xor_sync(0xffffffffu, s, o);
        s2 += __shfl_xor_sync(0xffffffffu, s2, o);
    }
    __shared__ float red[16];
    __shared__ float mv[2];
    int warp = tid >> 5, lane = tid & 31;
    if (lane == 0) { red[warp] = s; red[warp + 8] = s2; }
    __syncthreads();
    if (tid == 0) {
        float a = 0.f, b2 = 0.f;
        #pragma unroll
        for (int i = 0; i < 8; i++) { a += red[i]; b2 += red[i + 8]; }
        float mu  = a / (float)Ee;
        float var = b2 / (float)Ee - mu * mu;
        mv[0] = mu; mv[1] = rsqrtf(var + 1e-5f);
    }
    __syncthreads();
    float mu = mv[0], rs = mv[1];
    const float4* wv4 = reinterpret_cast<const float4*>(w);
    const float4* bv4 = reinterpret_cast<const float4*>(bias);
    uint2* outH = reinterpret_cast<uint2*>(g_hsH + (size_t)row * Ee);
    uint2* outL = reinterpret_cast<uint2*>(g_hsL + (size_t)row * Ee);
    {
        float4 wv = wv4[tid], bv = bv4[tid], o;
        o.x = (v0.x - mu) * rs * wv.x + bv.x;
        o.y = (v0.y - mu) * rs * wv.y + bv.y;
        o.z = (v0.z - mu) * rs * wv.z + bv.z;
        o.w = (v0.w - mu) * rs * wv.w + bv.w;
        uint32_t h0, l0, h1, l1;
        splitp_h(o.x, o.y, h0, l0); splitp_h(o.z, o.w, h1, l1);
        outH[tid] = make_uint2(h0, h1);
        outL[tid] = make_uint2(l0, l1);
    }
    {
        float4 wv = wv4[tid + 256], bv = bv4[tid + 256], o;
        o.x = (v1.x - mu) * rs * wv.x + bv.x;
        o.y = (v1.y - mu) * rs * wv.y + bv.y;
        o.z = (v1.z - mu) * rs * wv.z + bv.z;
        o.w = (v1.w - mu) * rs * wv.w + bv.w;
        uint32_t h0, l0, h1, l1;
        splitp_h(o.x, o.y, h0, l0); splitp_h(o.z, o.w, h1, l1);
        outH[tid + 256] = make_uint2(h0, h1);
        outL[tid + 256] = make_uint2(l0, l1);
    }
}

// ---------------- last non-pad index ----------------
__global__ __launch_bounds__(256) void ix_kernel(const int* __restrict__ ids) {
    int b = blockIdx.x;
    int m = -1;
    for (int s = threadIdx.x; s < Ss; s += 256)
        if (ids[b * Ss + s] != PADTOK) m = s;
    #pragma unroll
    for (int o = 16; o; o >>= 1) m = max(m, __shfl_xor_sync(0xffffffffu, m, o));
    __shared__ int rm[8];
    int warp = threadIdx.x >> 5, lane = threadIdx.x & 31;
    if (lane == 0) rm[warp] = m;
    __syncthreads();
    if (threadIdx.x == 0) {
        int mm = -1;
        #pragma unroll
        for (int i = 0; i < 8; i++) mm = max(mm, rm[i]);
        g_ix[b] = (mm < 0) ? 0 : mm;
    }
}

// ---------------- fused q + P-matrix kernel (per (h, b) block) ----------------
__global__ __launch_bounds__(256) void qpmat_kernel(const float* __restrict__ qw,
                                                    const float* __restrict__ qb,
                                                    const float* __restrict__ kw) {
    __shared__ float qs[128];
    const int tid = threadIdx.x, warp = tid >> 5, lane = tid & 31;
    const int h = blockIdx.x, b = blockIdx.y;

    size_t hb = ((size_t)(b * Ss) + g_ix[b]) * Ee;
    const uint2* hH = reinterpret_cast<const uint2*>(g_hsH + hb);
    const uint2* hL = reinterpret_cast<const uint2*>(g_hsL + hb);

    for (int rr = 0; rr < 16; rr++) {
        int d = warp * 16 + rr;
        int j = h * 128 + d;
        const float4* wrow = reinterpret_cast<const float4*>(qw + (size_t)j * Ee);
        float acc = 0.f;
        #pragma unroll
        for (int it = 0; it < 16; it++) {
            int i4 = it * 32 + lane;
            uint2 hv = hH[i4], lv = hL[i4];
            float4 w = wrow[i4];
            acc += h2sum(hv.x, lv.x, 0) * w.x;
            acc += h2sum(hv.x, lv.x, 1) * w.y;
            acc += h2sum(hv.y, lv.y, 0) * w.z;
            acc += h2sum(hv.y, lv.y, 1) * w.w;
        }
        #pragma unroll
        for (int o = 16; o; o >>= 1) acc += __shfl_xor_sync(0xffffffffu, acc, o);
        if (lane == 0) {
            float v = acc + qb[j];
            qs[d] = v;
            g_q[b * Ee + j] = v;
        }
    }
    __syncthreads();

    #pragma unroll
    for (int i = 0; i < 8; i++) {
        int e = tid + 256 * i;
        size_t pbase = ((size_t)(b * Hh + h)) * 64 * Ee + e;
        const float* kwb = kw + (size_t)h * Dd * Ee + e;
        #pragma unroll 4
        for (int j = 0; j < 32; j++) {
            float k0 = kwb[(size_t)(2 * j) * Ee];
            float k1 = kwb[(size_t)(2 * j + 1) * Ee];
            float A  = k0 * qs[2 * j]     + k1 * qs[2 * j + 1];
            float Bv = k0 * qs[2 * j + 1] - k1 * qs[2 * j];
            g_pH[pbase + (size_t)j * Ee] = __float2half_rn(A);
            g_pH[pbase + (size_t)(32 + j) * Ee] = __float2half_rn(Bv);
            g_pF[pbase + (size_t)j * Ee] = A;
            g_pF[pbase + (size_t)(32 + j) * Ee] = Bv;
        }
        float C = 0.f;
        #pragma unroll 8
        for (int d = 64; d < 128; d++) C += kwb[(size_t)d * Ee] * qs[d];
        g_Cv[(size_t)(b * Hh + h) * Ee + e] = C;
    }
}

// ---------------- GEMM G = hs @ P^T (2-term fp16: A split hi/lo, B single) -----
__device__ __forceinline__ void mma_f16(float c[4], uint32_t a0, uint32_t a1, uint32_t a2,
                                        uint32_t a3, uint32_t b0, uint32_t b1) {
    asm volatile(
        "mma.sync.aligned.m16n8k16.row.col.f32.f16.f16.f32 "
        "{%0,%1,%2,%3}, {%4,%5,%6,%7}, {%8,%9}, {%0,%1,%2,%3};"
        : "+f"(c[0]), "+f"(c[1]), "+f"(c[2]), "+f"(c[3])
        : "r"(a0), "r"(a1), "r"(a2), "r"(a3), "r"(b0), "r"(b1));
}

__device__ __forceinline__ void ldsm4(uint32_t r[4], uint32_t a) {
    asm volatile("ldmatrix.sync.aligned.m8n8.x4.shared.b16 {%0,%1,%2,%3}, [%4];"
                 : "=r"(r[0]), "=r"(r[1]), "=r"(r[2]), "=r"(r[3]) : "r"(a));
}

__device__ __forceinline__ void cp16(uint32_t dst, const void* src) {
    asm volatile("cp.async.cg.shared.global [%0], [%1], 16;" :: "r"(dst), "l"(src) : "memory");
}
#define CP_COMMIT() asm volatile("cp.async.commit_group;" ::: "memory")
#define CP_WAIT1()  asm volatile("cp.async.wait_group 1;" ::: "memory")
#define CP_WAIT0()  asm volatile("cp.async.wait_group 0;" ::: "memory")

// stage layout: A 128x128B per limb, B_H 64x128B
#define GA_H 0
#define GA_L 16384
#define GB_H 32768
#define GM_STAGE 40960
#define GEMM_SMEM (2 * GM_STAGE)   // 80 KB

__global__ void __launch_bounds__(256, 2) gemm_scores(const float* __restrict__ kb) {
    extern __shared__ char dsm[];
    __shared__ __align__(16) float pbA[32], pbB[32], pbCs[4];
    __shared__ __align__(16) double finv[32];
    __shared__ __align__(16) float Cs[2048];
    __shared__ __align__(16) float cred[128][2];

    const int tid = threadIdx.x, warp = tid >> 5, lane = tid & 31;
    const int bh = blockIdx.x, b = bh >> 4, h = bh & 15;   // bh fast: L2 A-sharing
    const int s0 = blockIdx.y * 128;

    if (tid < 32) {
        finv[tid] = exp(-((double)(2 * tid) / 64.0) * 9.210340371976184);
        float q0 = g_q[b * Ee + h * Dd + 2 * tid];
        float q1 = g_q[b * Ee + h * Dd + 2 * tid + 1];
        float k0 = kb[h * Dd + 2 * tid];
        float k1 = kb[h * Dd + 2 * tid + 1];
        pbA[tid] = q0 * k0 + q1 * k1;
        pbB[tid] = q1 * k0 - q0 * k1;
    } else if (tid == 32) {
        float a = 0.f;
        for (int d = 64; d < 128; d++) a += kb[h * Dd + d] * g_q[b * Ee + h * Dd + d];
        pbCs[0] = a;
    }
    {
        const float4* cv = reinterpret_cast<const float4*>(g_Cv + (size_t)bh * Ee);
        #pragma unroll
        for (int i = 0; i < 2; i++) {
            float4 v = cv[tid + i * 256];
            *reinterpret_cast<float4*>(&Cs[(tid + i * 256) * 4]) = v;
        }
    }

    uint32_t sb;
    asm("{ .reg .u64 t; cvta.to.shared.u64 t, %1; cvt.u32.u64 %0, t; }" : "=r"(sb) : "l"(dsm));

    const char* aHb = (const char*)(g_hsH + (size_t)(b * Ss + s0) * Ee);
    const char* aLb = (const char*)(g_hsL + (size_t)(b * Ss + s0) * Ee);
    const char* pHb = (const char*)(g_pH + (size_t)bh * 64 * Ee);

// 2560 cp16 per stage: A_H 0..1023, A_L 1024..2047, B_H 2048..2559
#define G_LOAD_STAGE(st, k0w)                                                     \
    {                                                                             \
        uint32_t sbase = sb + (st) * GM_STAGE;                                    \
        _Pragma("unroll")                                                         \
        for (int i = 0; i < 10; i++) {                                            \
            int id = tid + 256 * i;                                               \
            int arr = (id < 1024) ? 0 : (id < 2048) ? 1 : 2;                      \
            int rid = id - ((arr == 0) ? 0 : (arr == 1) ? 1024 : 2048);           \
            int row = rid >> 3, c = rid & 7;                                      \
            uint32_t aoff = (arr == 0) ? GA_H : (arr == 1) ? GA_L : GB_H;         \
            const char* src = (arr == 0) ? aHb : (arr == 1) ? aLb : pHb;          \
            uint32_t dst = sbase + aoff +                                         \
                (uint32_t)(row * 128 + ((c ^ (row & 7)) << 4));                   \
            cp16(dst, src + (size_t)row * 4096 + (size_t)(k0w) * 2 + c * 16);     \
        }                                                                         \
        CP_COMMIT();                                                              \
    }

    float acc[2][4][4];
    #pragma unroll
    for (int i = 0; i < 2; i++)
        #pragma unroll
        for (int j = 0; j < 4; j++)
            #pragma unroll
            for (int k = 0; k < 4; k++) acc[i][j][k] = 0.f;
    float cacc[2][2] = {{0.f, 0.f}, {0.f, 0.f}};

    const int warpM = warp >> 1, warpN = warp & 1;
    const int rA = warpM * 32, nbase = warpN * 32;
    const int g = lane >> 2, tq = lane & 3;

    G_LOAD_STAGE(0, 0);

    for (int k = 0; k < 32; k++) {
        const int s = k & 1;
        const int k0w = k * 64;
        if (k + 1 < 32) { G_LOAD_STAGE(s ^ 1, (k + 1) * 64); CP_WAIT1(); }
        else            { CP_WAIT0(); }
        __syncthreads();
        uint32_t base = sb + s * GM_STAGE;

        #pragma unroll
        for (int kk = 0; kk < 4; kk++) {
            const int kkc = kk * 2;
            uint32_t aH[2][4], aL[2][4];
            #pragma unroll
            for (int mt = 0; mt < 2; mt++) {
                int row = rA + mt * 16 + (lane & 15);
                int c16 = kkc + (lane >> 4);
                uint32_t off = (uint32_t)(row * 128 + ((c16 ^ (row & 7)) << 4));
                ldsm4(aH[mt], base + GA_H + off);
                ldsm4(aL[mt], base + GA_L + off);
            }
            uint32_t bH[8];
            #pragma unroll
            for (int tp = 0; tp < 2; tp++) {
                int row = nbase + tp * 16 + ((lane >> 4) << 3) + (lane & 7);
                int c16 = kkc + ((lane >> 3) & 1);
                uint32_t off = (uint32_t)(row * 128 + ((c16 ^ (row & 7)) << 4));
                ldsm4(&bH[tp * 4], base + GB_H + off);
            }
            if ((kk >> 1) == warpN) {
                #pragma unroll
                for (int mt = 0; mt < 2; mt++) {
                    #pragma unroll
                    for (int r = 0; r < 4; r++) {
                        float2 fh = __half22float2(*reinterpret_cast<__half2*>(&aH[mt][r]));
                        float2 fl = __half22float2(*reinterpret_cast<__half2*>(&aL[mt][r]));
                        int ki = k0w + kk * 16 + tq * 2 + ((r & 2) ? 8 : 0);
                        cacc[mt][r & 1] += (fh.x + fl.x) * Cs[ki] + (fh.y + fl.y) * Cs[ki + 1];
                    }
                }
            }
            #pragma unroll
            for (int nt = 0; nt < 4; nt++) {
                #pragma unroll
                for (int mt = 0; mt < 2; mt++) {
                    mma_f16(acc[mt][nt], aH[mt][0], aH[mt][1], aH[mt][2], aH[mt][3],
                            bH[nt * 2], bH[nt * 2 + 1]);
                    mma_f16(acc[mt][nt], aL[mt][0], aL[mt][1], aL[mt][2], aL[mt][3],
                            bH[nt * 2], bH[nt * 2 + 1]);
                }
            }
        }
        __syncthreads();
    }

    #pragma unroll
    for (int mt = 0; mt < 2; mt++) {
        #pragma unroll
        for (int rr = 0; rr < 2; rr++) {
            float p = cacc[mt][rr];
            p += __shfl_xor_sync(0xffffffffu, p, 1);
            p += __shfl_xor_sync(0xffffffffu, p, 2);
            if (tq == 0) cred[rA + mt * 16 + rr * 8 + g][warpN] = p;
        }
    }

    float* Gs = reinterpret_cast<float*>(dsm);   // [128][65]
    #pragma unroll
    for (int nt = 0; nt < 4; nt++) {
        #pragma unroll
        for (int mt = 0; mt < 2; mt++) {
            int r = rA + mt * 16 + (lane >> 2);
            int n = nbase + nt * 8 + 2 * (lane & 3);
            float* g0 = Gs + r * 65 + n;
            g0[0] = acc[mt][nt][0];
            g0[1] = acc[mt][nt][1];
            g0[65 * 8] = acc[mt][nt][2];
            g0[65 * 8 + 1] = acc[mt][nt][3];
        }
    }
    __syncthreads();
    if (tid < 128) {
        const double INV2PI = 0.15915494309189535;
        const double TWOPI  = 6.283185307179586;
        int s = s0 + tid;
        const float* row = Gs + tid * 65;
        float accS = cred[tid][0] + cred[tid][1] + pbCs[0];
        #pragma unroll 8
        for (int j = 0; j < 32; j++) {
            double ang = (double)s * finv[j];
            double kq = rint(ang * INV2PI);
            float r = (float)(ang - kq * TWOPI);
            float sn, cs;
            __sincosf(r, &sn, &cs);
            accS += cs * (row[j] + pbA[j]) + sn * (row[32 + j] + pbB[j]);
        }
        g_sc[(size_t)bh * Ss + s] = accS;
    }
}

// ---------------- top-32 selection (per b,h) ----------------
__global__ __launch_bounds__(256) void select_kernel() {
    __shared__ float msk[2048];
    __shared__ float redv[8];
    __shared__ int   redi[8];
    const int tid = threadIdx.x, warp = tid >> 5, lane = tid & 31;
    const int bh = blockIdx.x;

    #pragma unroll
    for (int i = 0; i < 8; i++)
        msk[tid + i * 256] = g_sc[(size_t)bh * Ss + tid + i * 256];
    __syncthreads();

    for (int it = 0; it < 32; it++) {
        float bv = -3e38f; int bi = 0;
        #pragma unroll
        for (int i = 0; i < 8; i++) {
            int idx = tid + i * 256;
            float v = msk[idx];
            if (v > bv) { bv = v; bi = idx; }
        }
        #pragma unroll
        for (int o = 16; o; o >>= 1) {
            float ov = __shfl_xor_sync(0xffffffffu, bv, o);
            int   oi = __shfl_xor_sync(0xffffffffu, bi, o);
            if (ov > bv || (ov == bv && oi < bi)) { bv = ov; bi = oi; }
        }
        if (lane == 0) { redv[warp] = bv; redi[warp] = bi; }
        __syncthreads();
        if (tid == 0) {
            float best = redv[0]; int besti = redi[0];
            #pragma unroll
            for (int i = 1; i < 8; i++)
                if (redv[i] > best || (redv[i] == best && redi[i] < besti)) {
                    best = redv[i]; besti = redi[i];
                }
            g_top[bh * 32 + it] = besti;
            msk[besti] = -3e38f;
        }
        __syncthreads();
    }
}

// ---------------- partial exact-G: grid (bh, kc) -------------------------------
#define SRP 261
#define RP_PC   0
#define RP_HC   (64 * SRP)
#define RP_CC   (RP_HC + 32 * SRP)
#define RP_TOT  (RP_CC + SRP)
#define RP_SMEM (RP_TOT * 4)

__global__ void __launch_bounds__(256, 1) refine_partial() {
    extern __shared__ float sm[];
    float* Pc = sm + RP_PC;
    float* Hc = sm + RP_HC;
    float* Cc = sm + RP_CC;
    __shared__ float Gt[32 * 68];
    __shared__ int topidx[32];

    const int tid = threadIdx.x;
    const int bh = blockIdx.x, kc = blockIdx.y;
    const int b = bh >> 4;

    if (tid < 32) topidx[tid] = g_top[bh * 32 + tid];
    __syncthreads();

    #pragma unroll
    for (int it = 0; it < 64; it++) {
        int flat = tid + 256 * it;
        int j = flat >> 8, i = flat & 255;
        Pc[j * SRP + i] = g_pF[((size_t)bh * 64 + j) * Ee + kc * 256 + i];
    }
    #pragma unroll
    for (int it = 0; it < 32; it++) {
        int flat = tid + 256 * it;
        int t = flat >> 8, i = flat & 255;
        size_t base = ((size_t)(b * Ss) + topidx[t]) * Ee + kc * 256 + i;
        Hc[t * SRP + i] = __half2float(g_hsH[base]) + __half2float(g_hsL[base]);
    }
    Cc[tid] = g_Cv[(size_t)bh * Ee + kc * 256 + tid];
    __syncthreads();

    float acc16[4][4];
    #pragma unroll
    for (int u = 0; u < 4; u++)
        #pragma unroll
        for (int v = 0; v < 4; v++) acc16[u][v] = 0.f;
    float Cacc = 0.f;
    const int kq = tid >> 7, rest = tid & 127;
    const int tg = rest >> 4, jg = rest & 15;

    #pragma unroll 4
    for (int ii = 0; ii < 128; ii++) {
        int kl = kq * 128 + ii;
        float pv[4], hv[4];
        #pragma unroll
        for (int u = 0; u < 4; u++) pv[u] = Pc[(jg + 16 * u) * SRP + kl];
        #pragma unroll
        for (int v = 0; v < 4; v++) hv[v] = Hc[(tg * 4 + v) * SRP + kl];
        #pragma unroll
        for (int u = 0; u < 4; u++)
            #pragma unroll
            for (int v = 0; v < 4; v++) acc16[u][v] += pv[u] * hv[v];
    }
    if (tid < 64) {
        int tC = tid >> 1, kqC = tid & 1;
        #pragma unroll 4
        for (int ii = 0; ii < 128; ii++)
            Cacc += Hc[tC * SRP + kqC * 128 + ii] * Cc[kqC * 128 + ii];
    }

    __syncthreads();
    if (kq == 0) {
        #pragma unroll
        for (int u = 0; u < 4; u++)
            #pragma unroll
            for (int v = 0; v < 4; v++)
                Gt[(tg * 4 + v) * 68 + jg + 16 * u] = acc16[u][v];
        if (tid < 64) Gt[(tid >> 1) * 68 + 64 + (tid & 1)] = Cacc;
    }
    __syncthreads();
    if (kq == 1) {
        #pragma unroll
        for (int u = 0; u < 4; u++)
            #pragma unroll
            for (int v = 0; v < 4; v++)
                Gt[(tg * 4 + v) * 68 + jg + 16 * u] += acc16[u][v];
    }
    __syncthreads();

    float* dst = g_Gp + ((size_t)bh * 8 + kc) * (32 * 68);
    #pragma unroll
    for (int i = 0; i < 9; i++) {
        int idx = tid + i * 256;
        if (idx < 32 * 68) dst[idx] = Gt[idx];
    }
}

// ---------------- finalize: exact top-32 logits + softmax (per b,h) -------------
__global__ void __launch_bounds__(256, 1) finalize_softmax(const float* __restrict__ kb) {
    __shared__ float sc[2048];
    __shared__ float G[32 * 68];
    __shared__ float pbA[32], pbB[32], pbCs[1];
    __shared__ double finv[32];
    __shared__ int topidx[32];
    __shared__ float redv[8];

    const int tid = threadIdx.x, warp = tid >> 5, lane = tid & 31;
    const int bh = blockIdx.x, b = bh >> 4, h = bh & 15;

    #pragma unroll
    for (int i = 0; i < 8; i++)
        sc[tid + i * 256] = g_sc[(size_t)bh * Ss + tid + i * 256];
    if (tid < 32) {
        topidx[tid] = g_top[bh * 32 + tid];
        finv[tid] = exp(-((double)(2 * tid) / 64.0) * 9.210340371976184);
        float q0 = g_q[b * Ee + h * Dd + 2 * tid];
        float q1 = g_q[b * Ee + h * Dd + 2 * tid + 1];
        float k0 = kb[h * Dd + 2 * tid];
        float k1 = kb[h * Dd + 2 * tid + 1];
        pbA[tid] = q0 * k0 + q1 * k1;
        pbB[tid] = q1 * k0 - q0 * k1;
    } else if (tid == 32) {
        float a = 0.f;
        for (int d = 64; d < 128; d++) a += kb[h * Dd + d] * g_q[b * Ee + h * Dd + d];
        pbCs[0] = a;
    }
    // sum the 8 partial G tiles
    {
        const float* src = g_Gp + (size_t)bh * 8 * (32 * 68);
        #pragma unroll
        for (int i = 0; i < 9; i++) {
            int idx = tid + i * 256;
            if (idx < 32 * 68) {
                float s = 0.f;
                #pragma unroll
                for (int p = 0; p < 8; p++) s += src[p * (32 * 68) + idx];
                G[idx] = s;
            }
        }
    }
    __syncthreads();

    // exact logits for the 32 tokens (warp per 4 tokens)
    {
        const double INV2PI = 0.15915494309189535;
        const double TWOPI  = 6.283185307179586;
        #pragma unroll
        for (int tt = 0; tt < 4; tt++) {
            int t = warp * 4 + tt;
            int s = topidx[t];
            double ang = (double)s * finv[lane];
            double kqd = rint(ang * INV2PI);
            float r = (float)(ang - kqd * TWOPI);
            float sn, cs;
            __sincosf(r, &sn, &cs);
            float val = cs * (G[t * 68 + lane] + pbA[lane])
                      + sn * (G[t * 68 + 32 + lane] + pbB[lane]);
            if (lane == 0) val += G[t * 68 + 64] + G[t * 68 + 65] + pbCs[0];
            #pragma unroll
            for (int o = 16; o; o >>= 1) val += __shfl_xor_sync(0xffffffffu, val, o);
            if (lane == 0) sc[s] = val;
        }
    }
    __syncthreads();

    // softmax over sc, write probs
    float v[8];
    float m = -3e38f;
    #pragma unroll
    for (int i = 0; i < 8; i++) { v[i] = sc[tid + i * 256]; m = fmaxf(m, v[i]); }
    #pragma unroll
    for (int o = 16; o; o >>= 1) m = fmaxf(m, __shfl_xor_sync(0xffffffffu, m, o));
    if (lane == 0) redv[warp] = m;
    __syncthreads();
    float mm = redv[0];
    #pragma unroll
    for (int i = 1; i < 8; i++) mm = fmaxf(mm, redv[i]);
    float ssum = 0.f;
    #pragma unroll
    for (int i = 0; i < 8; i++) { v[i] = expf(v[i] - mm); ssum += v[i]; }
    #pragma unroll
    for (int o = 16; o; o >>= 1) ssum += __shfl_xor_sync(0xffffffffu, ssum, o);
    __syncthreads();
    if (lane == 0) redv[warp] = ssum;
    __syncthreads();
    float tot = 0.f;
    #pragma unroll
    for (int i = 0; i < 8; i++) tot += redv[i];
    float inv = 1.f / tot;
    #pragma unroll
    for (int i = 0; i < 8; i++) g_sc[(size_t)bh * Ss + tid + i * 256] = v[i] * inv;
}

// ---------------- c[b,h,e] = sum_s attn * hs ----------------
__global__ void zero_c_kernel() {
    int i = blockIdx.x * blockDim.x + threadIdx.x;
    if (i < Bb * Hh * Ee) g_c[i] = 0.f;
}

__global__ __launch_bounds__(128) void cvec_kernel() {
    __shared__ float at[16][128];
    int tid = threadIdx.x;
    int b = blockIdx.y;
    int e = blockIdx.x * 128 + tid;
    int sbase = blockIdx.z * 256;
    float acc[16];
    #pragma unroll
    for (int i = 0; i < 16; i++) acc[i] = 0.f;
    for (int sc = 0; sc < 256; sc += 128) {
        #pragma unroll
        for (int i = 0; i < 16; i++) {
            int idx = tid + i * 128;
            int hh = idx >> 7, si = idx & 127;
            at[hh][si] = g_sc[(size_t)(b * Hh + hh) * Ss + sbase + sc + si];
        }
        __syncthreads();
        size_t base = (size_t)(b * Ss + sbase + sc) * Ee + e;
        #pragma unroll 4
        for (int si = 0; si < 128; si++) {
            float x = __half2float(g_hsH[base + (size_t)si * Ee])
                    + __half2float(g_hsL[base + (size_t)si * Ee]);
            #pragma unroll
            for (int hh = 0; hh < 16; hh++) acc[hh] += at[hh][si] * x;
        }
        __syncthreads();
    }
    #pragma unroll
    for (int hh = 0; hh < 16; hh++)
        atomicAdd(&g_c[(size_t)(b * Hh + hh) * Ee + e], acc[hh]);
}

// ---------------- out_attn = c @ v_w.T (per head) + v_b ----------------
__global__ __launch_bounds__(256) void vproj_kernel(const float* __restrict__ vw,
                                                    const float* __restrict__ vb) {
    int b = blockIdx.y;
    int warp = threadIdx.x >> 5, lane = threadIdx.x & 31;
    int j = blockIdx.x * 8 + warp;
    int hh = j >> 7;
    const float4* crow = reinterpret_cast<const float4*>(g_c + (size_t)(b * Hh + hh) * Ee);
    const float4* wrow = reinterpret_cast<const float4*>(vw + (size_t)j * Ee);
    float acc = 0.f;
    #pragma unroll
    for (int it = 0; it < 16; it++) {
        int i4 = it * 32 + lane;
        float4 a = crow[i4], w = wrow[i4];
        acc += a.x * w.x + a.y * w.y + a.z * w.z + a.w * w.w;
    }
    #pragma unroll
    for (int o = 16; o; o >>= 1) acc += __shfl_xor_sync(0xffffffffu, acc, o);
    if (lane == 0) g_oattn[b * Ee + j] = acc + vb[j];
}

// ---------------- out = out_attn @ out_w.T + out_b ----------------
__global__ __launch_bounds__(256) void oproj_kernel(const float* __restrict__ ow,
                                                    const float* __restrict__ ob,
                                                    float* __restrict__ out) {
    int b = blockIdx.y;
    int warp = threadIdx.x >> 5, lane = threadIdx.x & 31;
    int j = blockIdx.x * 8 + warp;
    const float4* arow = reinterpret_cast<const float4*>(g_oattn + (size_t)b * Ee);
    const float4* wrow = reinterpret_cast<const float4*>(ow + (size_t)j * Ee);
    float acc = 0.f;
    #pragma unroll
    for (int it = 0; it < 16; it++) {
        int i4 = it * 32 + lane;
        float4 a = arow[i4], w = wrow[i4];
        acc += a.x * w.x + a.y * w.y + a.z * w.z + a.w * w.w;
    }
    #pragma unroll
    for (int o = 16; o; o >>= 1) acc += __shfl_xor_sync(0xffffffffu, acc, o);
    if (lane == 0) out[b * Ee + j] = acc + ob[j];
}

// ---------------- launch ----------------
extern "C" void kernel_launch(void* const* d_in, const int* in_sizes, int n_in,
                              void* d_out, int out_size) {
    const float* hs_in = (const float*)d_in[0];
    const int*   ids   = (const int*)d_in[1];
    const float* lnw = (const float*)d_in[2];
    const float* lnb = (const float*)d_in[3];
    const float* qw  = (const float*)d_in[4];
    const float* qb  = (const float*)d_in[5];
    const float* kw  = (const float*)d_in[6];
    const float* kb  = (const float*)d_in[7];
    const float* vw  = (const float*)d_in[8];
    const float* vb  = (const float*)d_in[9];
    const float* ow  = (const float*)d_in[10];
    const float* ob  = (const float*)d_in[11];
    float* out = (float*)d_out;

    cudaFuncSetAttribute(gemm_scores, cudaFuncAttributeMaxDynamicSharedMemorySize, GEMM_SMEM);
    cudaFuncSetAttribute(refine_partial, cudaFuncAttributeMaxDynamicSharedMemorySize, RP_SMEM);

    ln_kernel<<<Bb * Ss, 256>>>(hs_in, lnw, lnb);
    ix_kernel<<<Bb, 256>>>(ids);
    qpmat_kernel<<<dim3(Hh, Bb), 256>>>(qw, qb, kw);
    gemm_scores<<<dim3(Bb * Hh, Ss / 128), 256, GEMM_SMEM>>>(kb);
    select_kernel<<<Bb * Hh, 256>>>();
    refine_partial<<<dim3(Bb * Hh, 8), 256, RP_SMEM>>>();
    finalize_softmax<<<Bb * Hh, 256>>>(kb);
    zero_c_kernel<<<(Bb * Hh * Ee + 255) / 256, 256>>>();
    cvec_kernel<<<dim3(Ee / 128, Bb, 8), 128>>>();
    vproj_kernel<<<dim3(Ee / 8, Bb), 256>>>(vw, vb);
    oproj_kernel<<<dim3(Ee / 8, Bb), 256>>>(ow, ob, out);
}

// round 13
// speedup vs baseline: 1.7208x; 1.1562x over previous
#include <cuda_runtime.h>
#include <cuda_fp16.h>
#include <cstdint>
#include <math.h>

#define Bb 8
#define Ss 2048
#define Ee 2048
#define Hh 16
#define Dd 128
#define PADTOK 50257

// ---------------- scratch (device globals: allocation-free) ----------------
__device__ __half g_hsH[(size_t)Bb * Ss * Ee];      // hi fp16 split of LN output
__device__ __half g_hsL[(size_t)Bb * Ss * Ee];      // lo fp16 split
__device__ __half g_pH[(size_t)Bb * Hh * 64 * Ee];  // projected weights fp16 (cos/sin coeffs)
__device__ float  g_pF[(size_t)Bb * Hh * 64 * Ee];  // projected weights fp32 (for refine)
__device__ float g_Cv[(size_t)Bb * Hh * Ee];        // C vector per (b,h), fp32
__device__ float g_q[Bb * Ee];
__device__ float g_sc[Bb * Hh * Ss];
__device__ float g_c[Bb * Hh * Ee];
__device__ float g_oattn[Bb * Ee];
__device__ int   g_ix[Bb];
__device__ int   g_top[Bb * Hh * 32];               // top-32 indices per bh
__device__ float g_Gp[(size_t)Bb * Hh * 8 * 32 * 68];  // partial G tiles (bh, kc)

// ---------------- helpers ----------------
__device__ __forceinline__ void splitp_h(float f0, float f1, uint32_t& hi, uint32_t& lo) {
    __half2 Hv = __floats2half2_rn(f0, f1);
    float r0 = f0 - __low2float(Hv);
    float r1 = f1 - __high2float(Hv);
    __half2 Lv = __floats2half2_rn(r0, r1);
    hi = *reinterpret_cast<uint32_t*>(&Hv);
    lo = *reinterpret_cast<uint32_t*>(&Lv);
}

__device__ __forceinline__ float h2sum(uint32_t h, uint32_t l, int sel) {
    __half2 hv = *reinterpret_cast<__half2*>(&h);
    __half2 lv = *reinterpret_cast<__half2*>(&l);
    return sel ? (__high2float(hv) + __high2float(lv))
               : (__low2float(hv) + __low2float(lv));
}

// ---------------- LayerNorm + fp16 hi/lo split ----------------
__global__ __launch_bounds__(256) void ln_kernel(const float* __restrict__ x,
                                                 const float* __restrict__ w,
                                                 const float* __restrict__ bias) {
    int row = blockIdx.x;
    const float4* xin = reinterpret_cast<const float4*>(x + (size_t)row * Ee);
    int tid = threadIdx.x;
    float4 v0 = xin[tid];
    float4 v1 = xin[tid + 256];
    float s  = v0.x + v0.y + v0.z + v0.w + v1.x + v1.y + v1.z + v1.w;
    float s2 = v0.x*v0.x + v0.y*v0.y + v0.z*v0.z + v0.w*v0.w
             + v1.x*v1.x + v1.y*v1.y + v1.z*v1.z + v1.w*v1.w;
    #pragma unroll
    for (int o = 16; o; o >>= 1) {
        s  += __shfl_xor_sync(0xffffffffu, s, o);
        s2 += __shfl_xor_sync(0xffffffffu, s2, o);
    }
    __shared__ float red[16];
    __shared__ float mv[2];
    int warp = tid >> 5, lane = tid & 31;
    if (lane == 0) { red[warp] = s; red[warp + 8] = s2; }
    __syncthreads();
    if (tid == 0) {
        float a = 0.f, b2 = 0.f;
        #pragma unroll
        for (int i = 0; i < 8; i++) { a += red[i]; b2 += red[i + 8]; }
        float mu  = a / (float)Ee;
        float var = b2 / (float)Ee - mu * mu;
        mv[0] = mu; mv[1] = rsqrtf(var + 1e-5f);
    }
    __syncthreads();
    float mu = mv[0], rs = mv[1];
    const float4* wv4 = reinterpret_cast<const float4*>(w);
    const float4* bv4 = reinterpret_cast<const float4*>(bias);
    uint2* outH = reinterpret_cast<uint2*>(g_hsH + (size_t)row * Ee);
    uint2* outL = reinterpret_cast<uint2*>(g_hsL + (size_t)row * Ee);
    {
        float4 wv = wv4[tid], bv = bv4[tid], o;
        o.x = (v0.x - mu) * rs * wv.x + bv.x;
        o.y = (v0.y - mu) * rs * wv.y + bv.y;
        o.z = (v0.z - mu) * rs * wv.z + bv.z;
        o.w = (v0.w - mu) * rs * wv.w + bv.w;
        uint32_t h0, l0, h1, l1;
        splitp_h(o.x, o.y, h0, l0); splitp_h(o.z, o.w, h1, l1);
        outH[tid] = make_uint2(h0, h1);
        outL[tid] = make_uint2(l0, l1);
    }
    {
        float4 wv = wv4[tid + 256], bv = bv4[tid + 256], o;
        o.x = (v1.x - mu) * rs * wv.x + bv.x;
        o.y = (v1.y - mu) * rs * wv.y + bv.y;
        o.z = (v1.z - mu) * rs * wv.z + bv.z;
        o.w = (v1.w - mu) * rs * wv.w + bv.w;
        uint32_t h0, l0, h1, l1;
        splitp_h(o.x, o.y, h0, l0); splitp_h(o.z, o.w, h1, l1);
        outH[tid + 256] = make_uint2(h0, h1);
        outL[tid + 256] = make_uint2(l0, l1);
    }
}

// ---------------- last non-pad index ----------------
__global__ __launch_bounds__(256) void ix_kernel(const int* __restrict__ ids) {
    int b = blockIdx.x;
    int m = -1;
    for (int s = threadIdx.x; s < Ss; s += 256)
        if (ids[b * Ss + s] != PADTOK) m = s;
    #pragma unroll
    for (int o = 16; o; o >>= 1) m = max(m, __shfl_xor_sync(0xffffffffu, m, o));
    __shared__ int rm[8];
    int warp = threadIdx.x >> 5, lane = threadIdx.x & 31;
    if (lane == 0) rm[warp] = m;
    __syncthreads();
    if (threadIdx.x == 0) {
        int mm = -1;
        #pragma unroll
        for (int i = 0; i < 8; i++) mm = max(mm, rm[i]);
        g_ix[b] = (mm < 0) ? 0 : mm;
    }
}

// ---------------- q = h_last @ q_w.T + q_b ----------------
__global__ __launch_bounds__(256) void q_kernel(const float* __restrict__ qw,
                                                const float* __restrict__ qb) {
    int b = blockIdx.y;
    int warp = threadIdx.x >> 5, lane = threadIdx.x & 31;
    int j = blockIdx.x * 8 + warp;
    size_t hb = ((size_t)(b * Ss) + g_ix[b]) * Ee;
    const uint2* hH = reinterpret_cast<const uint2*>(g_hsH + hb);
    const uint2* hL = reinterpret_cast<const uint2*>(g_hsL + hb);
    const float4* wrow = reinterpret_cast<const float4*>(qw + (size_t)j * Ee);
    float acc = 0.f;
    #pragma unroll
    for (int it = 0; it < 16; it++) {
        int i4 = it * 32 + lane;
        uint2 hv = hH[i4], lv = hL[i4];
        float4 w = wrow[i4];
        acc += h2sum(hv.x, lv.x, 0) * w.x;
        acc += h2sum(hv.x, lv.x, 1) * w.y;
        acc += h2sum(hv.y, lv.y, 0) * w.z;
        acc += h2sum(hv.y, lv.y, 1) * w.w;
    }
    #pragma unroll
    for (int o = 16; o; o >>= 1) acc += __shfl_xor_sync(0xffffffffu, acc, o);
    if (lane == 0) g_q[b * Ee + j] = acc + qb[j];
}

// ---------------- P matrices: fold q into k_w (RoPE projection) ----------------
// P[bh][n][e]: n<32: cos-coeff A_j; 32<=n<64: sin-coeff B_j.  Also fp32 copy + C.
__global__ __launch_bounds__(256) void pmat_kernel(const float* __restrict__ kw) {
    int tid = threadIdx.x;
    int e = blockIdx.x * 256 + tid;
    int h = blockIdx.y, b = blockIdx.z;
    __shared__ float qs[128];
    if (tid < 128) qs[tid] = g_q[b * Ee + h * Dd + tid];
    __syncthreads();
    size_t pbase = ((size_t)(b * Hh + h)) * 64 * Ee + e;
    const float* kwb = kw + (size_t)h * Dd * Ee + e;
    #pragma unroll 4
    for (int j = 0; j < 32; j++) {
        float k0 = kwb[(size_t)(2 * j) * Ee];
        float k1 = kwb[(size_t)(2 * j + 1) * Ee];
        float A  = k0 * qs[2 * j]     + k1 * qs[2 * j + 1];
        float Bv = k0 * qs[2 * j + 1] - k1 * qs[2 * j];
        g_pH[pbase + (size_t)j * Ee] = __float2half_rn(A);
        g_pH[pbase + (size_t)(32 + j) * Ee] = __float2half_rn(Bv);
        g_pF[pbase + (size_t)j * Ee] = A;
        g_pF[pbase + (size_t)(32 + j) * Ee] = Bv;
    }
    float C = 0.f;
    #pragma unroll 8
    for (int d = 64; d < 128; d++) C += kwb[(size_t)d * Ee] * qs[d];
    g_Cv[(size_t)(b * Hh + h) * Ee + e] = C;
}

// ---------------- GEMM G = hs @ P^T (2-term fp16: A split hi/lo, B single) -----
__device__ __forceinline__ void mma_f16(float c[4], uint32_t a0, uint32_t a1, uint32_t a2,
                                        uint32_t a3, uint32_t b0, uint32_t b1) {
    asm volatile(
        "mma.sync.aligned.m16n8k16.row.col.f32.f16.f16.f32 "
        "{%0,%1,%2,%3}, {%4,%5,%6,%7}, {%8,%9}, {%0,%1,%2,%3};"
        : "+f"(c[0]), "+f"(c[1]), "+f"(c[2]), "+f"(c[3])
        : "r"(a0), "r"(a1), "r"(a2), "r"(a3), "r"(b0), "r"(b1));
}

__device__ __forceinline__ void ldsm4(uint32_t r[4], uint32_t a) {
    asm volatile("ldmatrix.sync.aligned.m8n8.x4.shared.b16 {%0,%1,%2,%3}, [%4];"
                 : "=r"(r[0]), "=r"(r[1]), "=r"(r[2]), "=r"(r[3]) : "r"(a));
}

__device__ __forceinline__ void cp16(uint32_t dst, const void* src) {
    asm volatile("cp.async.cg.shared.global [%0], [%1], 16;" :: "r"(dst), "l"(src) : "memory");
}
#define CP_COMMIT() asm volatile("cp.async.commit_group;" ::: "memory")
#define CP_WAIT1()  asm volatile("cp.async.wait_group 1;" ::: "memory")
#define CP_WAIT0()  asm volatile("cp.async.wait_group 0;" ::: "memory")

// stage layout: A 128x128B per limb, B_H 64x128B
#define GA_H 0
#define GA_L 16384
#define GB_H 32768
#define GM_STAGE 40960
#define GEMM_SMEM (2 * GM_STAGE)   // 80 KB

__global__ void __launch_bounds__(256, 2) gemm_scores(const float* __restrict__ kb) {
    extern __shared__ char dsm[];
    __shared__ __align__(16) float pbA[32], pbB[32], pbCs[4];
    __shared__ __align__(16) double finv[32];
    __shared__ __align__(16) float Cs[2048];
    __shared__ __align__(16) float cred[128][2];

    const int tid = threadIdx.x, warp = tid >> 5, lane = tid & 31;
    const int bh = blockIdx.x, b = bh >> 4, h = bh & 15;   // bh fast: L2 A-sharing
    const int s0 = blockIdx.y * 128;

    if (tid < 32) {
        finv[tid] = exp(-((double)(2 * tid) / 64.0) * 9.210340371976184);
        float q0 = g_q[b * Ee + h * Dd + 2 * tid];
        float q1 = g_q[b * Ee + h * Dd + 2 * tid + 1];
        float k0 = kb[h * Dd + 2 * tid];
        float k1 = kb[h * Dd + 2 * tid + 1];
        pbA[tid] = q0 * k0 + q1 * k1;
        pbB[tid] = q1 * k0 - q0 * k1;
    } else if (tid == 32) {
        float a = 0.f;
        for (int d = 64; d < 128; d++) a += kb[h * Dd + d] * g_q[b * Ee + h * Dd + d];
        pbCs[0] = a;
    }
    {
        const float4* cv = reinterpret_cast<const float4*>(g_Cv + (size_t)bh * Ee);
        #pragma unroll
        for (int i = 0; i < 2; i++) {
            float4 v = cv[tid + i * 256];
            *reinterpret_cast<float4*>(&Cs[(tid + i * 256) * 4]) = v;
        }
    }

    uint32_t sb;
    asm("{ .reg .u64 t; cvta.to.shared.u64 t, %1; cvt.u32.u64 %0, t; }" : "=r"(sb) : "l"(dsm));

    const char* aHb = (const char*)(g_hsH + (size_t)(b * Ss + s0) * Ee);
    const char* aLb = (const char*)(g_hsL + (size_t)(b * Ss + s0) * Ee);
    const char* pHb = (const char*)(g_pH + (size_t)bh * 64 * Ee);

// 2560 cp16 per stage: A_H 0..1023, A_L 1024..2047, B_H 2048..2559
#define G_LOAD_STAGE(st, k0w)                                                     \
    {                                                                             \
        uint32_t sbase = sb + (st) * GM_STAGE;                                    \
        _Pragma("unroll")                                                         \
        for (int i = 0; i < 10; i++) {                                            \
            int id = tid + 256 * i;                                               \
            int arr = (id < 1024) ? 0 : (id < 2048) ? 1 : 2;                      \
            int rid = id - ((arr == 0) ? 0 : (arr == 1) ? 1024 : 2048);           \
            int row = rid >> 3, c = rid & 7;                                      \
            uint32_t aoff = (arr == 0) ? GA_H : (arr == 1) ? GA_L : GB_H;         \
            const char* src = (arr == 0) ? aHb : (arr == 1) ? aLb : pHb;          \
            uint32_t dst = sbase + aoff +                                         \
                (uint32_t)(row * 128 + ((c ^ (row & 7)) << 4));                   \
            cp16(dst, src + (size_t)row * 4096 + (size_t)(k0w) * 2 + c * 16);     \
        }                                                                         \
        CP_COMMIT();                                                              \
    }

    float acc[2][4][4];
    #pragma unroll
    for (int i = 0; i < 2; i++)
        #pragma unroll
        for (int j = 0; j < 4; j++)
            #pragma unroll
            for (int k = 0; k < 4; k++) acc[i][j][k] = 0.f;
    float cacc[2][2] = {{0.f, 0.f}, {0.f, 0.f}};

    const int warpM = warp >> 1, warpN = warp & 1;
    const int rA = warpM * 32, nbase = warpN * 32;
    const int g = lane >> 2, tq = lane & 3;

    G_LOAD_STAGE(0, 0);

    for (int k = 0; k < 32; k++) {
        const int s = k & 1;
        const int k0w = k * 64;
        if (k + 1 < 32) { G_LOAD_STAGE(s ^ 1, (k + 1) * 64); CP_WAIT1(); }
        else            { CP_WAIT0(); }
        __syncthreads();
        uint32_t base = sb + s * GM_STAGE;

        #pragma unroll
        for (int kk = 0; kk < 4; kk++) {
            const int kkc = kk * 2;
            uint32_t aH[2][4], aL[2][4];
            #pragma unroll
            for (int mt = 0; mt < 2; mt++) {
                int row = rA + mt * 16 + (lane & 15);
                int c16 = kkc + (lane >> 4);
                uint32_t off = (uint32_t)(row * 128 + ((c16 ^ (row & 7)) << 4));
                ldsm4(aH[mt], base + GA_H + off);
                ldsm4(aL[mt], base + GA_L + off);
            }
            uint32_t bH[8];
            #pragma unroll
            for (int tp = 0; tp < 2; tp++) {
                int row = nbase + tp * 16 + ((lane >> 4) << 3) + (lane & 7);
                int c16 = kkc + ((lane >> 3) & 1);
                uint32_t off = (uint32_t)(row * 128 + ((c16 ^ (row & 7)) << 4));
                ldsm4(&bH[tp * 4], base + GB_H + off);
            }
            if ((kk >> 1) == warpN) {
                #pragma unroll
                for (int mt = 0; mt < 2; mt++) {
                    #pragma unroll
                    for (int r = 0; r < 4; r++) {
                        float2 fh = __half22float2(*reinterpret_cast<__half2*>(&aH[mt][r]));
                        float2 fl = __half22float2(*reinterpret_cast<__half2*>(&aL[mt][r]));
                        int ki = k0w + kk * 16 + tq * 2 + ((r & 2) ? 8 : 0);
                        cacc[mt][r & 1] += (fh.x + fl.x) * Cs[ki] + (fh.y + fl.y) * Cs[ki + 1];
                    }
                }
            }
            #pragma unroll
            for (int nt = 0; nt < 4; nt++) {
                #pragma unroll
                for (int mt = 0; mt < 2; mt++) {
                    mma_f16(acc[mt][nt], aH[mt][0], aH[mt][1], aH[mt][2], aH[mt][3],
                            bH[nt * 2], bH[nt * 2 + 1]);
                    mma_f16(acc[mt][nt], aL[mt][0], aL[mt][1], aL[mt][2], aL[mt][3],
                            bH[nt * 2], bH[nt * 2 + 1]);
                }
            }
        }
        __syncthreads();
    }

    #pragma unroll
    for (int mt = 0; mt < 2; mt++) {
        #pragma unroll
        for (int rr = 0; rr < 2; rr++) {
            float p = cacc[mt][rr];
            p += __shfl_xor_sync(0xffffffffu, p, 1);
            p += __shfl_xor_sync(0xffffffffu, p, 2);
            if (tq == 0) cred[rA + mt * 16 + rr * 8 + g][warpN] = p;
        }
    }

    float* Gs = reinterpret_cast<float*>(dsm);   // [128][65]
    #pragma unroll
    for (int nt = 0; nt < 4; nt++) {
        #pragma unroll
        for (int mt = 0; mt < 2; mt++) {
            int r = rA + mt * 16 + (lane >> 2);
            int n = nbase + nt * 8 + 2 * (lane & 3);
            float* g0 = Gs + r * 65 + n;
            g0[0] = acc[mt][nt][0];
            g0[1] = acc[mt][nt][1];
            g0[65 * 8] = acc[mt][nt][2];
            g0[65 * 8 + 1] = acc[mt][nt][3];
        }
    }
    __syncthreads();
    if (tid < 128) {
        const double INV2PI = 0.15915494309189535;
        const double TWOPI  = 6.283185307179586;
        int s = s0 + tid;
        const float* row = Gs + tid * 65;
        float accS = cred[tid][0] + cred[tid][1] + pbCs[0];
        #pragma unroll 8
        for (int j = 0; j < 32; j++) {
            double ang = (double)s * finv[j];
            double kq = rint(ang * INV2PI);
            float r = (float)(ang - kq * TWOPI);
            float sn, cs;
            __sincosf(r, &sn, &cs);
            accS += cs * (row[j] + pbA[j]) + sn * (row[32 + j] + pbB[j]);
        }
        g_sc[(size_t)bh * Ss + s] = accS;
    }
}

// ---------------- top-32 selection (per b,h) ----------------
__global__ __launch_bounds__(256) void select_kernel() {
    __shared__ float msk[2048];
    __shared__ float redv[8];
    __shared__ int   redi[8];
    const int tid = threadIdx.x, warp = tid >> 5, lane = tid & 31;
    const int bh = blockIdx.x;

    #pragma unroll
    for (int i = 0; i < 8; i++)
        msk[tid + i * 256] = g_sc[(size_t)bh * Ss + tid + i * 256];
    __syncthreads();

    for (int it = 0; it < 32; it++) {
        float bv = -3e38f; int bi = 0;
        #pragma unroll
        for (int i = 0; i < 8; i++) {
            int idx = tid + i * 256;
            float v = msk[idx];
            if (v > bv) { bv = v; bi = idx; }
        }
        #pragma unroll
        for (int o = 16; o; o >>= 1) {
            float ov = __shfl_xor_sync(0xffffffffu, bv, o);
            int   oi = __shfl_xor_sync(0xffffffffu, bi, o);
            if (ov > bv || (ov == bv && oi < bi)) { bv = ov; bi = oi; }
        }
        if (lane == 0) { redv[warp] = bv; redi[warp] = bi; }
        __syncthreads();
        if (tid == 0) {
            float best = redv[0]; int besti = redi[0];
            #pragma unroll
            for (int i = 1; i < 8; i++)
                if (redv[i] > best || (redv[i] == best && redi[i] < besti)) {
                    best = redv[i]; besti = redi[i];
                }
            g_top[bh * 32 + it] = besti;
            msk[besti] = -3e38f;
        }
        __syncthreads();
    }
}

// ---------------- partial exact-G: grid (bh, kc) -------------------------------
#define SRP 261
#define RP_PC   0
#define RP_HC   (64 * SRP)
#define RP_CC   (RP_HC + 32 * SRP)
#define RP_TOT  (RP_CC + SRP)
#define RP_SMEM (RP_TOT * 4)

__global__ void __launch_bounds__(256, 1) refine_partial() {
    extern __shared__ float sm[];
    float* Pc = sm + RP_PC;
    float* Hc = sm + RP_HC;
    float* Cc = sm + RP_CC;
    __shared__ float Gt[32 * 68];
    __shared__ int topidx[32];

    const int tid = threadIdx.x;
    const int bh = blockIdx.x, kc = blockIdx.y;
    const int b = bh >> 4;

    if (tid < 32) topidx[tid] = g_top[bh * 32 + tid];
    __syncthreads();

    #pragma unroll
    for (int it = 0; it < 64; it++) {
        int flat = tid + 256 * it;
        int j = flat >> 8, i = flat & 255;
        Pc[j * SRP + i] = g_pF[((size_t)bh * 64 + j) * Ee + kc * 256 + i];
    }
    #pragma unroll
    for (int it = 0; it < 32; it++) {
        int flat = tid + 256 * it;
        int t = flat >> 8, i = flat & 255;
        size_t base = ((size_t)(b * Ss) + topidx[t]) * Ee + kc * 256 + i;
        Hc[t * SRP + i] = __half2float(g_hsH[base]) + __half2float(g_hsL[base]);
    }
    Cc[tid] = g_Cv[(size_t)bh * Ee + kc * 256 + tid];
    __syncthreads();

    float acc16[4][4];
    #pragma unroll
    for (int u = 0; u < 4; u++)
        #pragma unroll
        for (int v = 0; v < 4; v++) acc16[u][v] = 0.f;
    float Cacc = 0.f;
    const int kq = tid >> 7, rest = tid & 127;
    const int tg = rest >> 4, jg = rest & 15;

    #pragma unroll 4
    for (int ii = 0; ii < 128; ii++) {
        int kl = kq * 128 + ii;
        float pv[4], hv[4];
        #pragma unroll
        for (int u = 0; u < 4; u++) pv[u] = Pc[(jg + 16 * u) * SRP + kl];
        #pragma unroll
        for (int v = 0; v < 4; v++) hv[v] = Hc[(tg * 4 + v) * SRP + kl];
        #pragma unroll
        for (int u = 0; u < 4; u++)
            #pragma unroll
            for (int v = 0; v < 4; v++) acc16[u][v] += pv[u] * hv[v];
    }
    if (tid < 64) {
        int tC = tid >> 1, kqC = tid & 1;
        #pragma unroll 4
        for (int ii = 0; ii < 128; ii++)
            Cacc += Hc[tC * SRP + kqC * 128 + ii] * Cc[kqC * 128 + ii];
    }

    __syncthreads();
    if (kq == 0) {
        #pragma unroll
        for (int u = 0; u < 4; u++)
            #pragma unroll
            for (int v = 0; v < 4; v++)
                Gt[(tg * 4 + v) * 68 + jg + 16 * u] = acc16[u][v];
        if (tid < 64) Gt[(tid >> 1) * 68 + 64 + (tid & 1)] = Cacc;
    }
    __syncthreads();
    if (kq == 1) {
        #pragma unroll
        for (int u = 0; u < 4; u++)
            #pragma unroll
            for (int v = 0; v < 4; v++)
                Gt[(tg * 4 + v) * 68 + jg + 16 * u] += acc16[u][v];
    }
    __syncthreads();

    float* dst = g_Gp + ((size_t)bh * 8 + kc) * (32 * 68);
    #pragma unroll
    for (int i = 0; i < 9; i++) {
        int idx = tid + i * 256;
        if (idx < 32 * 68) dst[idx] = Gt[idx];
    }
}

// ---------------- finalize: exact top-32 logits + softmax (per b,h) -------------
__global__ void __launch_bounds__(256, 1) finalize_softmax(const float* __restrict__ kb) {
    __shared__ float sc[2048];
    __shared__ float G[32 * 68];
    __shared__ float pbA[32], pbB[32], pbCs[1];
    __shared__ double finv[32];
    __shared__ int topidx[32];
    __shared__ float redv[8];

    const int tid = threadIdx.x, warp = tid >> 5, lane = tid & 31;
    const int bh = blockIdx.x, b = bh >> 4, h = bh & 15;

    #pragma unroll
    for (int i = 0; i < 8; i++)
        sc[tid + i * 256] = g_sc[(size_t)bh * Ss + tid + i * 256];
    if (tid < 32) {
        topidx[tid] = g_top[bh * 32 + tid];
        finv[tid] = exp(-((double)(2 * tid) / 64.0) * 9.210340371976184);
        float q0 = g_q[b * Ee + h * Dd + 2 * tid];
        float q1 = g_q[b * Ee + h * Dd + 2 * tid + 1];
        float k0 = kb[h * Dd + 2 * tid];
        float k1 = kb[h * Dd + 2 * tid + 1];
        pbA[tid] = q0 * k0 + q1 * k1;
        pbB[tid] = q1 * k0 - q0 * k1;
    } else if (tid == 32) {
        float a = 0.f;
        for (int d = 64; d < 128; d++) a += kb[h * Dd + d] * g_q[b * Ee + h * Dd + d];
        pbCs[0] = a;
    }
    // sum the 8 partial G tiles
    {
        const float* src = g_Gp + (size_t)bh * 8 * (32 * 68);
        #pragma unroll
        for (int i = 0; i < 9; i++) {
            int idx = tid + i * 256;
            if (idx < 32 * 68) {
                float s = 0.f;
                #pragma unroll
                for (int p = 0; p < 8; p++) s += src[p * (32 * 68) + idx];
                G[idx] = s;
            }
        }
    }
    __syncthreads();

    // exact logits for the 32 tokens (warp per 4 tokens)
    {
        const double INV2PI = 0.15915494309189535;
        const double TWOPI  = 6.283185307179586;
        #pragma unroll
        for (int tt = 0; tt < 4; tt++) {
            int t = warp * 4 + tt;
            int s = topidx[t];
            double ang = (double)s * finv[lane];
            double kqd = rint(ang * INV2PI);
            float r = (float)(ang - kqd * TWOPI);
            float sn, cs;
            __sincosf(r, &sn, &cs);
            float val = cs * (G[t * 68 + lane] + pbA[lane])
                      + sn * (G[t * 68 + 32 + lane] + pbB[lane]);
            if (lane == 0) val += G[t * 68 + 64] + G[t * 68 + 65] + pbCs[0];
            #pragma unroll
            for (int o = 16; o; o >>= 1) val += __shfl_xor_sync(0xffffffffu, val, o);
            if (lane == 0) sc[s] = val;
        }
    }
    __syncthreads();

    // softmax over sc, write probs
    float v[8];
    float m = -3e38f;
    #pragma unroll
    for (int i = 0; i < 8; i++) { v[i] = sc[tid + i * 256]; m = fmaxf(m, v[i]); }
    #pragma unroll
    for (int o = 16; o; o >>= 1) m = fmaxf(m, __shfl_xor_sync(0xffffffffu, m, o));
    if (lane == 0) redv[warp] = m;
    __syncthreads();
    float mm = redv[0];
    #pragma unroll
    for (int i = 1; i < 8; i++) mm = fmaxf(mm, redv[i]);
    float ssum = 0.f;
    #pragma unroll
    for (int i = 0; i < 8; i++) { v[i] = expf(v[i] - mm); ssum += v[i]; }
    #pragma unroll
    for (int o = 16; o; o >>= 1) ssum += __shfl_xor_sync(0xffffffffu, ssum, o);
    __syncthreads();
    if (lane == 0) redv[warp] = ssum;
    __syncthreads();
    float tot = 0.f;
    #pragma unroll
    for (int i = 0; i < 8; i++) tot += redv[i];
    float inv = 1.f / tot;
    #pragma unroll
    for (int i = 0; i < 8; i++) g_sc[(size_t)bh * Ss + tid + i * 256] = v[i] * inv;
}

// ---------------- c[b,h,e] = sum_s attn * hs ----------------
__global__ void zero_c_kernel() {
    int i = blockIdx.x * blockDim.x + threadIdx.x;
    if (i < Bb * Hh * Ee) g_c[i] = 0.f;
}

__global__ __launch_bounds__(128) void cvec_kernel() {
    __shared__ float at[16][128];
    int tid = threadIdx.x;
    int b = blockIdx.y;
    int e = blockIdx.x * 128 + tid;
    int sbase = blockIdx.z * 256;
    float acc[16];
    #pragma unroll
    for (int i = 0; i < 16; i++) acc[i] = 0.f;
    for (int sc = 0; sc < 256; sc += 128) {
        #pragma unroll
        for (int i = 0; i < 16; i++) {
            int idx = tid + i * 128;
            int hh = idx >> 7, si = idx & 127;
            at[hh][si] = g_sc[(size_t)(b * Hh + hh) * Ss + sbase + sc + si];
        }
        __syncthreads();
        size_t base = (size_t)(b * Ss + sbase + sc) * Ee + e;
        #pragma unroll 4
        for (int si = 0; si < 128; si++) {
            float x = __half2float(g_hsH[base + (size_t)si * Ee])
                    + __half2float(g_hsL[base + (size_t)si * Ee]);
            #pragma unroll
            for (int hh = 0; hh < 16; hh++) acc[hh] += at[hh][si] * x;
        }
        __syncthreads();
    }
    #pragma unroll
    for (int hh = 0; hh < 16; hh++)
        atomicAdd(&g_c[(size_t)(b * Hh + hh) * Ee + e], acc[hh]);
}

// ---------------- out_attn = c @ v_w.T (per head) + v_b ----------------
__global__ __launch_bounds__(256) void vproj_kernel(const float* __restrict__ vw,
                                                    const float* __restrict__ vb) {
    int b = blockIdx.y;
    int warp = threadIdx.x >> 5, lane = threadIdx.x & 31;
    int j = blockIdx.x * 8 + warp;
    int hh = j >> 7;
    const float4* crow = reinterpret_cast<const float4*>(g_c + (size_t)(b * Hh + hh) * Ee);
    const float4* wrow = reinterpret_cast<const float4*>(vw + (size_t)j * Ee);
    float acc = 0.f;
    #pragma unroll
    for (int it = 0; it < 16; it++) {
        int i4 = it * 32 + lane;
        float4 a = crow[i4], w = wrow[i4];
        acc += a.x * w.x + a.y * w.y + a.z * w.z + a.w * w.w;
    }
    #pragma unroll
    for (int o = 16; o; o >>= 1) acc += __shfl_xor_sync(0xffffffffu, acc, o);
    if (lane == 0) g_oattn[b * Ee + j] = acc + vb[j];
}

// ---------------- out = out_attn @ out_w.T + out_b ----------------
__global__ __launch_bounds__(256) void oproj_kernel(const float* __restrict__ ow,
                                                    const float* __restrict__ ob,
                                                    float* __restrict__ out) {
    int b = blockIdx.y;
    int warp = threadIdx.x >> 5, lane = threadIdx.x & 31;
    int j = blockIdx.x * 8 + warp;
    const float4* arow = reinterpret_cast<const float4*>(g_oattn + (size_t)b * Ee);
    const float4* wrow = reinterpret_cast<const float4*>(ow + (size_t)j * Ee);
    float acc = 0.f;
    #pragma unroll
    for (int it = 0; it < 16; it++) {
        int i4 = it * 32 + lane;
        float4 a = arow[i4], w = wrow[i4];
        acc += a.x * w.x + a.y * w.y + a.z * w.z + a.w * w.w;
    }
    #pragma unroll
    for (int o = 16; o; o >>= 1) acc += __shfl_xor_sync(0xffffffffu, acc, o);
    if (lane == 0) out[b * Ee + j] = acc + ob[j];
}

// ---------------- launch ----------------
extern "C" void kernel_launch(void* const* d_in, const int* in_sizes, int n_in,
                              void* d_out, int out_size) {
    const float* hs_in = (const float*)d_in[0];
    const int*   ids   = (const int*)d_in[1];
    const float* lnw = (const float*)d_in[2];
    const float* lnb = (const float*)d_in[3];
    const float* qw  = (const float*)d_in[4];
    const float* qb  = (const float*)d_in[5];
    const float* kw  = (const float*)d_in[6];
    const float* kb  = (const float*)d_in[7];
    const float* vw  = (const float*)d_in[8];
    const float* vb  = (const float*)d_in[9];
    const float* ow  = (const float*)d_in[10];
    const float* ob  = (const float*)d_in[11];
    float* out = (float*)d_out;

    cudaFuncSetAttribute(gemm_scores, cudaFuncAttributeMaxDynamicSharedMemorySize, GEMM_SMEM);
    cudaFuncSetAttribute(refine_partial, cudaFuncAttributeMaxDynamicSharedMemorySize, RP_SMEM);

    ln_kernel<<<Bb * Ss, 256>>>(hs_in, lnw, lnb);
    ix_kernel<<<Bb, 256>>>(ids);
    q_kernel<<<dim3(Ee / 8, Bb), 256>>>(qw, qb);
    pmat_kernel<<<dim3(Ee / 256, Hh, Bb), 256>>>(kw);
    gemm_scores<<<dim3(Bb * Hh, Ss / 128), 256, GEMM_SMEM>>>(kb);
    select_kernel<<<Bb * Hh, 256>>>();
    refine_partial<<<dim3(Bb * Hh, 8), 256, RP_SMEM>>>();
    finalize_softmax<<<Bb * Hh, 256>>>(kb);
    zero_c_kernel<<<(Bb * Hh * Ee + 255) / 256, 256>>>();
    cvec_kernel<<<dim3(Ee / 128, Bb, 8), 128>>>();
    vproj_kernel<<<dim3(Ee / 8, Bb), 256>>>(vw, vb);
    oproj_kernel<<<dim3(Ee / 8, Bb), 256>>>(ow, ob, out);
}

// round 14
// speedup vs baseline: 2.2866x; 1.3288x over previous
#include <cuda_runtime.h>
#include <cuda_fp16.h>
#include <cstdint>
#include <math.h>

#define Bb 8
#define Ss 2048
#define Ee 2048
#define Hh 16
#define Dd 128
#define PADTOK 50257

// ---------------- scratch (device globals: allocation-free) ----------------
__device__ __half g_hsH[(size_t)Bb * Ss * Ee];      // hi fp16 split of LN output
__device__ __half g_hsL[(size_t)Bb * Ss * Ee];      // lo fp16 split
__device__ __half g_pH[(size_t)Bb * Hh * 64 * Ee];  // projected weights fp16 (cos/sin coeffs)
__device__ float  g_pF[(size_t)Bb * Hh * 64 * Ee];  // projected weights fp32 (for refine)
__device__ float g_Cv[(size_t)Bb * Hh * Ee];        // C vector per (b,h), fp32
__device__ float g_q[Bb * Ee];
__device__ float g_sc[Bb * Hh * Ss];
__device__ float g_c[Bb * Hh * Ee];
__device__ float g_oattn[Bb * Ee];
__device__ int   g_ix[Bb];
__device__ int   g_top[Bb * Hh * 32];               // top-32 indices per bh
__device__ float g_Gp[(size_t)Bb * Hh * 8 * 32 * 68];  // partial G tiles (bh, kc)

// ---------------- helpers ----------------
__device__ __forceinline__ void splitp_h(float f0, float f1, uint32_t& hi, uint32_t& lo) {
    __half2 Hv = __floats2half2_rn(f0, f1);
    float r0 = f0 - __low2float(Hv);
    float r1 = f1 - __high2float(Hv);
    __half2 Lv = __floats2half2_rn(r0, r1);
    hi = *reinterpret_cast<uint32_t*>(&Hv);
    lo = *reinterpret_cast<uint32_t*>(&Lv);
}

__device__ __forceinline__ float h2sum(uint32_t h, uint32_t l, int sel) {
    __half2 hv = *reinterpret_cast<__half2*>(&h);
    __half2 lv = *reinterpret_cast<__half2*>(&l);
    return sel ? (__high2float(hv) + __high2float(lv))
               : (__low2float(hv) + __low2float(lv));
}

// ---------------- LayerNorm + fp16 hi/lo split ----------------
__global__ __launch_bounds__(256) void ln_kernel(const float* __restrict__ x,
                                                 const float* __restrict__ w,
                                                 const float* __restrict__ bias) {
    int row = blockIdx.x;
    const float4* xin = reinterpret_cast<const float4*>(x + (size_t)row * Ee);
    int tid = threadIdx.x;
    float4 v0 = xin[tid];
    float4 v1 = xin[tid + 256];
    float s  = v0.x + v0.y + v0.z + v0.w + v1.x + v1.y + v1.z + v1.w;
    float s2 = v0.x*v0.x + v0.y*v0.y + v0.z*v0.z + v0.w*v0.w
             + v1.x*v1.x + v1.y*v1.y + v1.z*v1.z + v1.w*v1.w;
    #pragma unroll
    for (int o = 16; o; o >>= 1) {
        s  += __shfl_xor_sync(0xffffffffu, s, o);
        s2 += __shfl_xor_sync(0xffffffffu, s2, o);
    }
    __shared__ float red[16];
    __shared__ float mv[2];
    int warp = tid >> 5, lane = tid & 31;
    if (lane == 0) { red[warp] = s; red[warp + 8] = s2; }
    __syncthreads();
    if (tid == 0) {
        float a = 0.f, b2 = 0.f;
        #pragma unroll
        for (int i = 0; i < 8; i++) { a += red[i]; b2 += red[i + 8]; }
        float mu  = a / (float)Ee;
        float var = b2 / (float)Ee - mu * mu;
        mv[0] = mu; mv[1] = rsqrtf(var + 1e-5f);
    }
    __syncthreads();
    float mu = mv[0], rs = mv[1];
    const float4* wv4 = reinterpret_cast<const float4*>(w);
    const float4* bv4 = reinterpret_cast<const float4*>(bias);
    uint2* outH = reinterpret_cast<uint2*>(g_hsH + (size_t)row * Ee);
    uint2* outL = reinterpret_cast<uint2*>(g_hsL + (size_t)row * Ee);
    {
        float4 wv = wv4[tid], bv = bv4[tid], o;
        o.x = (v0.x - mu) * rs * wv.x + bv.x;
        o.y = (v0.y - mu) * rs * wv.y + bv.y;
        o.z = (v0.z - mu) * rs * wv.z + bv.z;
        o.w = (v0.w - mu) * rs * wv.w + bv.w;
        uint32_t h0, l0, h1, l1;
        splitp_h(o.x, o.y, h0, l0); splitp_h(o.z, o.w, h1, l1);
        outH[tid] = make_uint2(h0, h1);
        outL[tid] = make_uint2(l0, l1);
    }
    {
        float4 wv = wv4[tid + 256], bv = bv4[tid + 256], o;
        o.x = (v1.x - mu) * rs * wv.x + bv.x;
        o.y = (v1.y - mu) * rs * wv.y + bv.y;
        o.z = (v1.z - mu) * rs * wv.z + bv.z;
        o.w = (v1.w - mu) * rs * wv.w + bv.w;
        uint32_t h0, l0, h1, l1;
        splitp_h(o.x, o.y, h0, l0); splitp_h(o.z, o.w, h1, l1);
        outH[tid + 256] = make_uint2(h0, h1);
        outL[tid + 256] = make_uint2(l0, l1);
    }
}

// ---------------- last non-pad index ----------------
__global__ __launch_bounds__(256) void ix_kernel(const int* __restrict__ ids) {
    int b = blockIdx.x;
    int m = -1;
    for (int s = threadIdx.x; s < Ss; s += 256)
        if (ids[b * Ss + s] != PADTOK) m = s;
    #pragma unroll
    for (int o = 16; o; o >>= 1) m = max(m, __shfl_xor_sync(0xffffffffu, m, o));
    __shared__ int rm[8];
    int warp = threadIdx.x >> 5, lane = threadIdx.x & 31;
    if (lane == 0) rm[warp] = m;
    __syncthreads();
    if (threadIdx.x == 0) {
        int mm = -1;
        #pragma unroll
        for (int i = 0; i < 8; i++) mm = max(mm, rm[i]);
        g_ix[b] = (mm < 0) ? 0 : mm;
    }
}

// ---------------- q = h_last @ q_w.T + q_b ----------------
__global__ __launch_bounds__(256) void q_kernel(const float* __restrict__ qw,
                                                const float* __restrict__ qb) {
    int b = blockIdx.y;
    int warp = threadIdx.x >> 5, lane = threadIdx.x & 31;
    int j = blockIdx.x * 8 + warp;
    size_t hb = ((size_t)(b * Ss) + g_ix[b]) * Ee;
    const uint2* hH = reinterpret_cast<const uint2*>(g_hsH + hb);
    const uint2* hL = reinterpret_cast<const uint2*>(g_hsL + hb);
    const float4* wrow = reinterpret_cast<const float4*>(qw + (size_t)j * Ee);
    float acc = 0.f;
    #pragma unroll
    for (int it = 0; it < 16; it++) {
        int i4 = it * 32 + lane;
        uint2 hv = hH[i4], lv = hL[i4];
        float4 w = wrow[i4];
        acc += h2sum(hv.x, lv.x, 0) * w.x;
        acc += h2sum(hv.x, lv.x, 1) * w.y;
        acc += h2sum(hv.y, lv.y, 0) * w.z;
        acc += h2sum(hv.y, lv.y, 1) * w.w;
    }
    #pragma unroll
    for (int o = 16; o; o >>= 1) acc += __shfl_xor_sync(0xffffffffu, acc, o);
    if (lane == 0) g_q[b * Ee + j] = acc + qb[j];
}

// ---------------- P matrices: fold q into k_w (RoPE projection) ----------------
__global__ __launch_bounds__(256) void pmat_kernel(const float* __restrict__ kw) {
    int tid = threadIdx.x;
    int e = blockIdx.x * 256 + tid;
    int h = blockIdx.y, b = blockIdx.z;
    __shared__ float qs[128];
    if (tid < 128) qs[tid] = g_q[b * Ee + h * Dd + tid];
    __syncthreads();
    size_t pbase = ((size_t)(b * Hh + h)) * 64 * Ee + e;
    const float* kwb = kw + (size_t)h * Dd * Ee + e;
    #pragma unroll 4
    for (int j = 0; j < 32; j++) {
        float k0 = kwb[(size_t)(2 * j) * Ee];
        float k1 = kwb[(size_t)(2 * j + 1) * Ee];
        float A  = k0 * qs[2 * j]     + k1 * qs[2 * j + 1];
        float Bv = k0 * qs[2 * j + 1] - k1 * qs[2 * j];
        g_pH[pbase + (size_t)j * Ee] = __float2half_rn(A);
        g_pH[pbase + (size_t)(32 + j) * Ee] = __float2half_rn(Bv);
        g_pF[pbase + (size_t)j * Ee] = A;
        g_pF[pbase + (size_t)(32 + j) * Ee] = Bv;
    }
    float C = 0.f;
    #pragma unroll 8
    for (int d = 64; d < 128; d++) C += kwb[(size_t)d * Ee] * qs[d];
    g_Cv[(size_t)(b * Hh + h) * Ee + e] = C;
}

// ---------------- GEMM G = hs @ P^T (1-term fp16; exact top-32 refined later) ---
__device__ __forceinline__ void mma_f16(float c[4], uint32_t a0, uint32_t a1, uint32_t a2,
                                        uint32_t a3, uint32_t b0, uint32_t b1) {
    asm volatile(
        "mma.sync.aligned.m16n8k16.row.col.f32.f16.f16.f32 "
        "{%0,%1,%2,%3}, {%4,%5,%6,%7}, {%8,%9}, {%0,%1,%2,%3};"
        : "+f"(c[0]), "+f"(c[1]), "+f"(c[2]), "+f"(c[3])
        : "r"(a0), "r"(a1), "r"(a2), "r"(a3), "r"(b0), "r"(b1));
}

__device__ __forceinline__ void ldsm4(uint32_t r[4], uint32_t a) {
    asm volatile("ldmatrix.sync.aligned.m8n8.x4.shared.b16 {%0,%1,%2,%3}, [%4];"
                 : "=r"(r[0]), "=r"(r[1]), "=r"(r[2]), "=r"(r[3]) : "r"(a));
}

__device__ __forceinline__ void cp16(uint32_t dst, const void* src) {
    asm volatile("cp.async.cg.shared.global [%0], [%1], 16;" :: "r"(dst), "l"(src) : "memory");
}
#define CP_COMMIT() asm volatile("cp.async.commit_group;" ::: "memory")
#define CP_WAIT1()  asm volatile("cp.async.wait_group 1;" ::: "memory")
#define CP_WAIT0()  asm volatile("cp.async.wait_group 0;" ::: "memory")

// stage layout: A_H 128x128B, B_H 64x128B
#define GA_H 0
#define GB_H 16384
#define GM_STAGE 24576
#define GEMM_SMEM (2 * GM_STAGE)   // 48 KB

__global__ void __launch_bounds__(256, 2) gemm_scores(const float* __restrict__ kb) {
    extern __shared__ char dsm[];
    __shared__ __align__(16) float pbA[32], pbB[32], pbCs[4];
    __shared__ __align__(16) double finv[32];
    __shared__ __align__(16) float Cs[2048];
    __shared__ __align__(16) float cred[128][2];

    const int tid = threadIdx.x, warp = tid >> 5, lane = tid & 31;
    const int bh = blockIdx.x, b = bh >> 4, h = bh & 15;   // bh fast: L2 A-sharing
    const int s0 = blockIdx.y * 128;

    if (tid < 32) {
        finv[tid] = exp(-((double)(2 * tid) / 64.0) * 9.210340371976184);
        float q0 = g_q[b * Ee + h * Dd + 2 * tid];
        float q1 = g_q[b * Ee + h * Dd + 2 * tid + 1];
        float k0 = kb[h * Dd + 2 * tid];
        float k1 = kb[h * Dd + 2 * tid + 1];
        pbA[tid] = q0 * k0 + q1 * k1;
        pbB[tid] = q1 * k0 - q0 * k1;
    } else if (tid == 32) {
        float a = 0.f;
        for (int d = 64; d < 128; d++) a += kb[h * Dd + d] * g_q[b * Ee + h * Dd + d];
        pbCs[0] = a;
    }
    {
        const float4* cv = reinterpret_cast<const float4*>(g_Cv + (size_t)bh * Ee);
        #pragma unroll
        for (int i = 0; i < 2; i++) {
            float4 v = cv[tid + i * 256];
            *reinterpret_cast<float4*>(&Cs[(tid + i * 256) * 4]) = v;
        }
    }

    uint32_t sb;
    asm("{ .reg .u64 t; cvta.to.shared.u64 t, %1; cvt.u32.u64 %0, t; }" : "=r"(sb) : "l"(dsm));

    const char* aHb = (const char*)(g_hsH + (size_t)(b * Ss + s0) * Ee);
    const char* pHb = (const char*)(g_pH + (size_t)bh * 64 * Ee);

// 1536 cp16 per stage: A_H 0..1023, B_H 1024..1535
#define G_LOAD_STAGE(st, k0w)                                                     \
    {                                                                             \
        uint32_t sbase = sb + (st) * GM_STAGE;                                    \
        _Pragma("unroll")                                                         \
        for (int i = 0; i < 6; i++) {                                             \
            int id = tid + 256 * i;                                               \
            int arr = (id < 1024) ? 0 : 1;                                        \
            int rid = id - ((arr == 0) ? 0 : 1024);                               \
            int row = rid >> 3, c = rid & 7;                                      \
            uint32_t aoff = (arr == 0) ? GA_H : GB_H;                             \
            const char* src = (arr == 0) ? aHb : pHb;                             \
            uint32_t dst = sbase + aoff +                                         \
                (uint32_t)(row * 128 + ((c ^ (row & 7)) << 4));                   \
            cp16(dst, src + (size_t)row * 4096 + (size_t)(k0w) * 2 + c * 16);     \
        }                                                                         \
        CP_COMMIT();                                                              \
    }

    float acc[2][4][4];
    #pragma unroll
    for (int i = 0; i < 2; i++)
        #pragma unroll
        for (int j = 0; j < 4; j++)
            #pragma unroll
            for (int k = 0; k < 4; k++) acc[i][j][k] = 0.f;
    float cacc[2][2] = {{0.f, 0.f}, {0.f, 0.f}};

    const int warpM = warp >> 1, warpN = warp & 1;
    const int rA = warpM * 32, nbase = warpN * 32;
    const int g = lane >> 2, tq = lane & 3;

    G_LOAD_STAGE(0, 0);

    for (int k = 0; k < 32; k++) {
        const int s = k & 1;
        const int k0w = k * 64;
        if (k + 1 < 32) { G_LOAD_STAGE(s ^ 1, (k + 1) * 64); CP_WAIT1(); }
        else            { CP_WAIT0(); }
        __syncthreads();
        uint32_t base = sb + s * GM_STAGE;

        #pragma unroll
        for (int kk = 0; kk < 4; kk++) {
            const int kkc = kk * 2;
            uint32_t aH[2][4];
            #pragma unroll
            for (int mt = 0; mt < 2; mt++) {
                int row = rA + mt * 16 + (lane & 15);
                int c16 = kkc + (lane >> 4);
                uint32_t off = (uint32_t)(row * 128 + ((c16 ^ (row & 7)) << 4));
                ldsm4(aH[mt], base + GA_H + off);
            }
            uint32_t bH[8];
            #pragma unroll
            for (int tp = 0; tp < 2; tp++) {
                int row = nbase + tp * 16 + ((lane >> 4) << 3) + (lane & 7);
                int c16 = kkc + ((lane >> 3) & 1);
                uint32_t off = (uint32_t)(row * 128 + ((c16 ^ (row & 7)) << 4));
                ldsm4(&bH[tp * 4], base + GB_H + off);
            }
            // in-register C-dot on the fma pipe (hi limb only; exact for top-32 later)
            if ((kk >> 1) == warpN) {
                #pragma unroll
                for (int mt = 0; mt < 2; mt++) {
                    #pragma unroll
                    for (int r = 0; r < 4; r++) {
                        float2 fh = __half22float2(*reinterpret_cast<__half2*>(&aH[mt][r]));
                        int ki = k0w + kk * 16 + tq * 2 + ((r & 2) ? 8 : 0);
                        cacc[mt][r & 1] += fh.x * Cs[ki] + fh.y * Cs[ki + 1];
                    }
                }
            }
            #pragma unroll
            for (int nt = 0; nt < 4; nt++) {
                #pragma unroll
                for (int mt = 0; mt < 2; mt++) {
                    mma_f16(acc[mt][nt], aH[mt][0], aH[mt][1], aH[mt][2], aH[mt][3],
                            bH[nt * 2], bH[nt * 2 + 1]);
                }
            }
        }
        __syncthreads();
    }

    #pragma unroll
    for (int mt = 0; mt < 2; mt++) {
        #pragma unroll
        for (int rr = 0; rr < 2; rr++) {
            float p = cacc[mt][rr];
            p += __shfl_xor_sync(0xffffffffu, p, 1);
            p += __shfl_xor_sync(0xffffffffu, p, 2);
            if (tq == 0) cred[rA + mt * 16 + rr * 8 + g][warpN] = p;
        }
    }

    float* Gs = reinterpret_cast<float*>(dsm);   // [128][65] = 33280 B < 48 KB
    #pragma unroll
    for (int nt = 0; nt < 4; nt++) {
        #pragma unroll
        for (int mt = 0; mt < 2; mt++) {
            int r = rA + mt * 16 + (lane >> 2);
            int n = nbase + nt * 8 + 2 * (lane & 3);
            float* g0 = Gs + r * 65 + n;
            g0[0] = acc[mt][nt][0];
            g0[1] = acc[mt][nt][1];
            g0[65 * 8] = acc[mt][nt][2];
            g0[65 * 8 + 1] = acc[mt][nt][3];
        }
    }
    __syncthreads();
    if (tid < 128) {
        const double INV2PI = 0.15915494309189535;
        const double TWOPI  = 6.283185307179586;
        int s = s0 + tid;
        const float* row = Gs + tid * 65;
        float accS = cred[tid][0] + cred[tid][1] + pbCs[0];
        #pragma unroll 8
        for (int j = 0; j < 32; j++) {
            double ang = (double)s * finv[j];
            double kq = rint(ang * INV2PI);
            float r = (float)(ang - kq * TWOPI);
            float sn, cs;
            __sincosf(r, &sn, &cs);
            accS += cs * (row[j] + pbA[j]) + sn * (row[32 + j] + pbB[j]);
        }
        g_sc[(size_t)bh * Ss + s] = accS;
    }
}

// ---------------- top-32 selection (per b,h) ----------------
__global__ __launch_bounds__(256) void select_kernel() {
    __shared__ float msk[2048];
    __shared__ float redv[8];
    __shared__ int   redi[8];
    const int tid = threadIdx.x, warp = tid >> 5, lane = tid & 31;
    const int bh = blockIdx.x;

    #pragma unroll
    for (int i = 0; i < 8; i++)
        msk[tid + i * 256] = g_sc[(size_t)bh * Ss + tid + i * 256];
    __syncthreads();

    for (int it = 0; it < 32; it++) {
        float bv = -3e38f; int bi = 0;
        #pragma unroll
        for (int i = 0; i < 8; i++) {
            int idx = tid + i * 256;
            float v = msk[idx];
            if (v > bv) { bv = v; bi = idx; }
        }
        #pragma unroll
        for (int o = 16; o; o >>= 1) {
            float ov = __shfl_xor_sync(0xffffffffu, bv, o);
            int   oi = __shfl_xor_sync(0xffffffffu, bi, o);
            if (ov > bv || (ov == bv && oi < bi)) { bv = ov; bi = oi; }
        }
        if (lane == 0) { redv[warp] = bv; redi[warp] = bi; }
        __syncthreads();
        if (tid == 0) {
            float best = redv[0]; int besti = redi[0];
            #pragma unroll
            for (int i = 1; i < 8; i++)
                if (redv[i] > best || (redv[i] == best && redi[i] < besti)) {
                    best = redv[i]; besti = redi[i];
                }
            g_top[bh * 32 + it] = besti;
            msk[besti] = -3e38f;
        }
        __syncthreads();
    }
}

// ---------------- partial exact-G: grid (bh, kc) -------------------------------
#define SRP 261
#define RP_PC   0
#define RP_HC   (64 * SRP)
#define RP_CC   (RP_HC + 32 * SRP)
#define RP_TOT  (RP_CC + SRP)
#define RP_SMEM (RP_TOT * 4)

__global__ void __launch_bounds__(256, 1) refine_partial() {
    extern __shared__ float sm[];
    float* Pc = sm + RP_PC;
    float* Hc = sm + RP_HC;
    float* Cc = sm + RP_CC;
    __shared__ float Gt[32 * 68];
    __shared__ int topidx[32];

    const int tid = threadIdx.x;
    const int bh = blockIdx.x, kc = blockIdx.y;
    const int b = bh >> 4;

    if (tid < 32) topidx[tid] = g_top[bh * 32 + tid];
    __syncthreads();

    #pragma unroll
    for (int it = 0; it < 64; it++) {
        int flat = tid + 256 * it;
        int j = flat >> 8, i = flat & 255;
        Pc[j * SRP + i] = g_pF[((size_t)bh * 64 + j) * Ee + kc * 256 + i];
    }
    #pragma unroll
    for (int it = 0; it < 32; it++) {
        int flat = tid + 256 * it;
        int t = flat >> 8, i = flat & 255;
        size_t base = ((size_t)(b * Ss) + topidx[t]) * Ee + kc * 256 + i;
        Hc[t * SRP + i] = __half2float(g_hsH[base]) + __half2float(g_hsL[base]);
    }
    Cc[tid] = g_Cv[(size_t)bh * Ee + kc * 256 + tid];
    __syncthreads();

    float acc16[4][4];
    #pragma unroll
    for (int u = 0; u < 4; u++)
        #pragma unroll
        for (int v = 0; v < 4; v++) acc16[u][v] = 0.f;
    float Cacc = 0.f;
    const int kq = tid >> 7, rest = tid & 127;
    const int tg = rest >> 4, jg = rest & 15;

    #pragma unroll 4
    for (int ii = 0; ii < 128; ii++) {
        int kl = kq * 128 + ii;
        float pv[4], hv[4];
        #pragma unroll
        for (int u = 0; u < 4; u++) pv[u] = Pc[(jg + 16 * u) * SRP + kl];
        #pragma unroll
        for (int v = 0; v < 4; v++) hv[v] = Hc[(tg * 4 + v) * SRP + kl];
        #pragma unroll
        for (int u = 0; u < 4; u++)
            #pragma unroll
            for (int v = 0; v < 4; v++) acc16[u][v] += pv[u] * hv[v];
    }
    if (tid < 64) {
        int tC = tid >> 1, kqC = tid & 1;
        #pragma unroll 4
        for (int ii = 0; ii < 128; ii++)
            Cacc += Hc[tC * SRP + kqC * 128 + ii] * Cc[kqC * 128 + ii];
    }

    __syncthreads();
    if (kq == 0) {
        #pragma unroll
        for (int u = 0; u < 4; u++)
            #pragma unroll
            for (int v = 0; v < 4; v++)
                Gt[(tg * 4 + v) * 68 + jg + 16 * u] = acc16[u][v];
        if (tid < 64) Gt[(tid >> 1) * 68 + 64 + (tid & 1)] = Cacc;
    }
    __syncthreads();
    if (kq == 1) {
        #pragma unroll
        for (int u = 0; u < 4; u++)
            #pragma unroll
            for (int v = 0; v < 4; v++)
                Gt[(tg * 4 + v) * 68 + jg + 16 * u] += acc16[u][v];
    }
    __syncthreads();

    float* dst = g_Gp + ((size_t)bh * 8 + kc) * (32 * 68);
    #pragma unroll
    for (int i = 0; i < 9; i++) {
        int idx = tid + i * 256;
        if (idx < 32 * 68) dst[idx] = Gt[idx];
    }
}

// ---------------- finalize: exact top-32 logits + softmax (per b,h) -------------
__global__ void __launch_bounds__(256, 1) finalize_softmax(const float* __restrict__ kb) {
    __shared__ float sc[2048];
    __shared__ float G[32 * 68];
    __shared__ float pbA[32], pbB[32], pbCs[1];
    __shared__ double finv[32];
    __shared__ int topidx[32];
    __shared__ float redv[8];

    const int tid = threadIdx.x, warp = tid >> 5, lane = tid & 31;
    const int bh = blockIdx.x, b = bh >> 4, h = bh & 15;

    #pragma unroll
    for (int i = 0; i < 8; i++)
        sc[tid + i * 256] = g_sc[(size_t)bh * Ss + tid + i * 256];
    if (tid < 32) {
        topidx[tid] = g_top[bh * 32 + tid];
        finv[tid] = exp(-((double)(2 * tid) / 64.0) * 9.210340371976184);
        float q0 = g_q[b * Ee + h * Dd + 2 * tid];
        float q1 = g_q[b * Ee + h * Dd + 2 * tid + 1];
        float k0 = kb[h * Dd + 2 * tid];
        float k1 = kb[h * Dd + 2 * tid + 1];
        pbA[tid] = q0 * k0 + q1 * k1;
        pbB[tid] = q1 * k0 - q0 * k1;
    } else if (tid == 32) {
        float a = 0.f;
        for (int d = 64; d < 128; d++) a += kb[h * Dd + d] * g_q[b * Ee + h * Dd + d];
        pbCs[0] = a;
    }
    // sum the 8 partial G tiles
    {
        const float* src = g_Gp + (size_t)bh * 8 * (32 * 68);
        #pragma unroll
        for (int i = 0; i < 9; i++) {
            int idx = tid + i * 256;
            if (idx < 32 * 68) {
                float s = 0.f;
                #pragma unroll
                for (int p = 0; p < 8; p++) s += src[p * (32 * 68) + idx];
                G[idx] = s;
            }
        }
    }
    __syncthreads();

    // exact logits for the 32 tokens (warp per 4 tokens)
    {
        const double INV2PI = 0.15915494309189535;
        const double TWOPI  = 6.283185307179586;
        #pragma unroll
        for (int tt = 0; tt < 4; tt++) {
            int t = warp * 4 + tt;
            int s = topidx[t];
            double ang = (double)s * finv[lane];
            double kqd = rint(ang * INV2PI);
            float r = (float)(ang - kqd * TWOPI);
            float sn, cs;
            __sincosf(r, &sn, &cs);
            float val = cs * (G[t * 68 + lane] + pbA[lane])
                      + sn * (G[t * 68 + 32 + lane] + pbB[lane]);
            if (lane == 0) val += G[t * 68 + 64] + G[t * 68 + 65] + pbCs[0];
            #pragma unroll
            for (int o = 16; o; o >>= 1) val += __shfl_xor_sync(0xffffffffu, val, o);
            if (lane == 0) sc[s] = val;
        }
    }
    __syncthreads();

    // softmax over sc, write probs
    float v[8];
    float m = -3e38f;
    #pragma unroll
    for (int i = 0; i < 8; i++) { v[i] = sc[tid + i * 256]; m = fmaxf(m, v[i]); }
    #pragma unroll
    for (int o = 16; o; o >>= 1) m = fmaxf(m, __shfl_xor_sync(0xffffffffu, m, o));
    if (lane == 0) redv[warp] = m;
    __syncthreads();
    float mm = redv[0];
    #pragma unroll
    for (int i = 1; i < 8; i++) mm = fmaxf(mm, redv[i]);
    float ssum = 0.f;
    #pragma unroll
    for (int i = 0; i < 8; i++) { v[i] = expf(v[i] - mm); ssum += v[i]; }
    #pragma unroll
    for (int o = 16; o; o >>= 1) ssum += __shfl_xor_sync(0xffffffffu, ssum, o);
    __syncthreads();
    if (lane == 0) redv[warp] = ssum;
    __syncthreads();
    float tot = 0.f;
    #pragma unroll
    for (int i = 0; i < 8; i++) tot += redv[i];
    float inv = 1.f / tot;
    #pragma unroll
    for (int i = 0; i < 8; i++) g_sc[(size_t)bh * Ss + tid + i * 256] = v[i] * inv;
}

// ---------------- c[b,h,e] = sum_s attn * hs ----------------
__global__ void zero_c_kernel() {
    int i = blockIdx.x * blockDim.x + threadIdx.x;
    if (i < Bb * Hh * Ee) g_c[i] = 0.f;
}

__global__ __launch_bounds__(128) void cvec_kernel() {
    __shared__ float at[16][128];
    int tid = threadIdx.x;
    int b = blockIdx.y;
    int e = blockIdx.x * 128 + tid;
    int sbase = blockIdx.z * 256;
    float acc[16];
    #pragma unroll
    for (int i = 0; i < 16; i++) acc[i] = 0.f;
    for (int sc = 0; sc < 256; sc += 128) {
        #pragma unroll
        for (int i = 0; i < 16; i++) {
            int idx = tid + i * 128;
            int hh = idx >> 7, si = idx & 127;
            at[hh][si] = g_sc[(size_t)(b * Hh + hh) * Ss + sbase + sc + si];
        }
        __syncthreads();
        size_t base = (size_t)(b * Ss + sbase + sc) * Ee + e;
        #pragma unroll 4
        for (int si = 0; si < 128; si++) {
            float x = __half2float(g_hsH[base + (size_t)si * Ee])
                    + __half2float(g_hsL[base + (size_t)si * Ee]);
            #pragma unroll
            for (int hh = 0; hh < 16; hh++) acc[hh] += at[hh][si] * x;
        }
        __syncthreads();
    }
    #pragma unroll
    for (int hh = 0; hh < 16; hh++)
        atomicAdd(&g_c[(size_t)(b * Hh + hh) * Ee + e], acc[hh]);
}

// ---------------- out_attn = c @ v_w.T (per head) + v_b ----------------
__global__ __launch_bounds__(256) void vproj_kernel(const float* __restrict__ vw,
                                                    const float* __restrict__ vb) {
    int b = blockIdx.y;
    int warp = threadIdx.x >> 5, lane = threadIdx.x & 31;
    int j = blockIdx.x * 8 + warp;
    int hh = j >> 7;
    const float4* crow = reinterpret_cast<const float4*>(g_c + (size_t)(b * Hh + hh) * Ee);
    const float4* wrow = reinterpret_cast<const float4*>(vw + (size_t)j * Ee);
    float acc = 0.f;
    #pragma unroll
    for (int it = 0; it < 16; it++) {
        int i4 = it * 32 + lane;
        float4 a = crow[i4], w = wrow[i4];
        acc += a.x * w.x + a.y * w.y + a.z * w.z + a.w * w.w;
    }
    #pragma unroll
    for (int o = 16; o; o >>= 1) acc += __shfl_xor_sync(0xffffffffu, acc, o);
    if (lane == 0) g_oattn[b * Ee + j] = acc + vb[j];
}

// ---------------- out = out_attn @ out_w.T + out_b ----------------
__global__ __launch_bounds__(256) void oproj_kernel(const float* __restrict__ ow,
                                                    const float* __restrict__ ob,
                                                    float* __restrict__ out) {
    int b = blockIdx.y;
    int warp = threadIdx.x >> 5, lane = threadIdx.x & 31;
    int j = blockIdx.x * 8 + warp;
    const float4* arow = reinterpret_cast<const float4*>(g_oattn + (size_t)b * Ee);
    const float4* wrow = reinterpret_cast<const float4*>(ow + (size_t)j * Ee);
    float acc = 0.f;
    #pragma unroll
    for (int it = 0; it < 16; it++) {
        int i4 = it * 32 + lane;
        float4 a = arow[i4], w = wrow[i4];
        acc += a.x * w.x + a.y * w.y + a.z * w.z + a.w * w.w;
    }
    #pragma unroll
    for (int o = 16; o; o >>= 1) acc += __shfl_xor_sync(0xffffffffu, acc, o);
    if (lane == 0) out[b * Ee + j] = acc + ob[j];
}

// ---------------- launch ----------------
extern "C" void kernel_launch(void* const* d_in, const int* in_sizes, int n_in,
                              void* d_out, int out_size) {
    const float* hs_in = (const float*)d_in[0];
    const int*   ids   = (const int*)d_in[1];
    const float* lnw = (const float*)d_in[2];
    const float* lnb = (const float*)d_in[3];
    const float* qw  = (const float*)d_in[4];
    const float* qb  = (const float*)d_in[5];
    const float* kw  = (const float*)d_in[6];
    const float* kb  = (const float*)d_in[7];
    const float* vw  = (const float*)d_in[8];
    const float* vb  = (const float*)d_in[9];
    const float* ow  = (const float*)d_in[10];
    const float* ob  = (const float*)d_in[11];
    float* out = (float*)d_out;

    cudaFuncSetAttribute(gemm_scores, cudaFuncAttributeMaxDynamicSharedMemorySize, GEMM_SMEM);
    cudaFuncSetAttribute(refine_partial, cudaFuncAttributeMaxDynamicSharedMemorySize, RP_SMEM);

    ln_kernel<<<Bb * Ss, 256>>>(hs_in, lnw, lnb);
    ix_kernel<<<Bb, 256>>>(ids);
    q_kernel<<<dim3(Ee / 8, Bb), 256>>>(qw, qb);
    pmat_kernel<<<dim3(Ee / 256, Hh, Bb), 256>>>(kw);
    gemm_scores<<<dim3(Bb * Hh, Ss / 128), 256, GEMM_SMEM>>>(kb);
    select_kernel<<<Bb * Hh, 256>>>();
    refine_partial<<<dim3(Bb * Hh, 8), 256, RP_SMEM>>>();
    finalize_softmax<<<Bb * Hh, 256>>>(kb);
    zero_c_kernel<<<(Bb * Hh * Ee + 255) / 256, 256>>>();
    cvec_kernel<<<dim3(Ee / 128, Bb, 8), 128>>>();
    vproj_kernel<<<dim3(Ee / 8, Bb), 256>>>(vw, vb);
    oproj_kernel<<<dim3(Ee / 8, Bb), 256>>>(ow, ob, out);
}